// round 6
// baseline (speedup 1.0000x reference)
#include <cuda_runtime.h>
#include <cuda_bf16.h>
#include <math.h>
#include <stdint.h>

#define BB 8
#define CC 64
#define C4 256
#define H2 128
#define W2 128

typedef __nv_bfloat16 bf16;

// ---------------------------------------------------------------------------
// Global scratch
// ---------------------------------------------------------------------------
__device__ float g_t0[(size_t)BB * H2 * W2 * C4];     // dwt out / cv out (fp32 NHWC)
__device__ float g_t1[(size_t)BB * H2 * W2 * C4];     // pw out fp32 NHWC
__device__ bf16 g_a_hi[(size_t)BB * H2 * W2 * C4];    // dw out split (pw A)
__device__ bf16 g_a_lo[(size_t)BB * H2 * W2 * C4];
__device__ float g_dwT[9 * C4];
__device__ bf16 g_pw_hi[C4 * C4];                      // [oc][ic]
__device__ bf16 g_pw_lo[C4 * C4];

// int8 cv path: chunk-major swizzled tiles
#define ABLK 4160   // 32B guard + 128*32B + 32B guard
__device__ char g_qah[(size_t)BB * H2 * 8 * ABLK];     // [b][i][kb] guarded blocks
__device__ char g_qal[(size_t)BB * H2 * 8 * ABLK];
__device__ char g_cvBh[72 * 2 * 4096];                 // [tap*8+kb][ochalf] tiles
__device__ char g_cvBl[72 * 2 * 4096];
__device__ char g_zeroblk[ABLK];                       // never written -> stays 0
__device__ float g_sW[C4];
__device__ int g_amax;

__device__ __forceinline__ float gelu_exact(float v) {
    return 0.5f * v * (1.0f + erff(v * 0.70710678118654752f));
}
__device__ __forceinline__ uint32_t smem_to_u32(const void* p) {
    uint32_t a;
    asm("{ .reg .u64 t; cvta.to.shared.u64 t, %1; cvt.u32.u64 %0, t; }" : "=r"(a) : "l"(p));
    return a;
}

// ---- cp.async (per-thread, pw) ----
__device__ __forceinline__ void cpa16(uint32_t dst, const void* src, bool ok) {
    int sz = ok ? 16 : 0;
    asm volatile("cp.async.cg.shared.global [%0], [%1], 16, %2;\n"
                 :: "r"(dst), "l"(src), "r"(sz));
}
__device__ __forceinline__ void cpa_commit() {
    asm volatile("cp.async.commit_group;\n" ::: "memory");
}
template<int N>
__device__ __forceinline__ void cpa_wait() {
    asm volatile("cp.async.wait_group %0;\n" :: "n"(N) : "memory");
}

// ---- bulk copy + mbarrier (cv) ----
__device__ __forceinline__ void bulk_g2s(uint32_t dst, const void* src,
                                         uint32_t bytes, uint32_t mbar) {
    asm volatile(
        "cp.async.bulk.shared::cluster.global.mbarrier::complete_tx::bytes "
        "[%0], [%1], %2, [%3];"
        :: "r"(dst), "l"(src), "r"(bytes), "r"(mbar) : "memory");
}
#define MBARRIER_INIT(mbar, count) \
    asm volatile("mbarrier.init.shared.b64 [%0], %1;" :: "r"((uint32_t)(mbar)), "r"((uint32_t)(count)) : "memory")
#define MBARRIER_EXPECT_TX(mbar, bytes) \
    asm volatile("mbarrier.arrive.expect_tx.shared.b64 _, [%0], %1;" :: "r"((uint32_t)(mbar)), "r"((uint32_t)(bytes)) : "memory")
#define MBARRIER_WAIT_PARITY(mbar_smem_addr, phase_parity) do { \
    uint32_t _mbar = (uint32_t)(mbar_smem_addr); \
    uint32_t _parity = (uint32_t)(phase_parity); \
    uint32_t _done; \
    asm volatile("{\n\t.reg .pred p;\n\t" \
        "mbarrier.try_wait.parity.acquire.cta.shared::cta.b64 p, [%1], %2;\n\t" \
        "selp.b32 %0, 1, 0, p;\n\t}" : "=r"(_done) : "r"(_mbar), "r"(_parity) : "memory"); \
    if (!_done) { \
        asm volatile("{\n\t.reg .pred P1;\n\t" \
            "WAIT_LOOP_%=:\n\t" \
            "mbarrier.try_wait.parity.acquire.cta.shared::cta.b64 P1, [%0], %1, 0x989680;\n\t" \
            "@P1 bra.uni WAIT_DONE_%=;\n\t" \
            "bra.uni WAIT_LOOP_%=;\n\t" \
            "WAIT_DONE_%=:\n\t}" :: "r"(_mbar), "r"(_parity) : "memory"); \
    } \
} while(0)

// ---- mma ----
__device__ __forceinline__ void ldsm4(uint32_t* r, uint32_t addr) {
    asm volatile("ldmatrix.sync.aligned.m8n8.x4.shared.b16 {%0,%1,%2,%3}, [%4];"
                 : "=r"(r[0]), "=r"(r[1]), "=r"(r[2]), "=r"(r[3]) : "r"(addr));
}
__device__ __forceinline__ void mma16816(float* c, const uint32_t* a,
                                         uint32_t b0, uint32_t b1) {
    asm volatile(
        "mma.sync.aligned.m16n8k16.row.col.f32.bf16.bf16.f32 "
        "{%0,%1,%2,%3}, {%4,%5,%6,%7}, {%8,%9}, {%0,%1,%2,%3};"
        : "+f"(c[0]), "+f"(c[1]), "+f"(c[2]), "+f"(c[3])
        : "r"(a[0]), "r"(a[1]), "r"(a[2]), "r"(a[3]), "r"(b0), "r"(b1));
}
__device__ __forceinline__ void imma16832(int* c, const uint32_t* a,
                                          uint32_t b0, uint32_t b1) {
    asm volatile(
        "mma.sync.aligned.m16n8k32.row.col.s32.s8.s8.s32 "
        "{%0,%1,%2,%3}, {%4,%5,%6,%7}, {%8,%9}, {%0,%1,%2,%3};"
        : "+r"(c[0]), "+r"(c[1]), "+r"(c[2]), "+r"(c[3])
        : "r"(a[0]), "r"(a[1]), "r"(a[2]), "r"(a[3]), "r"(b0), "r"(b1));
}

// int8 tile pack addressing (swizzle baked in; conflict-free for ldmatrix)
__device__ __forceinline__ uint32_t packA(int jp, int ic5) {   // jp: 0..129
    int seg = ic5 >> 4, mic = ic5 & 15;
    return (uint32_t)(jp * 32 + ((seg ^ ((jp >> 2) & 1)) << 4) + mic);
}
__device__ __forceinline__ uint32_t packB(int oc7, int ic5) {  // oc7: 0..127
    int seg = ic5 >> 4, mic = ic5 & 15;
    return (uint32_t)(oc7 * 32 + ((seg ^ ((oc7 >> 2) & 1)) << 4) + mic);
}

// ---------------------------------------------------------------------------
// prep: amax reset, dw weights, pw bf16 split
// ---------------------------------------------------------------------------
__global__ void prep_kernel(const float* __restrict__ dw_w,
                            const float* __restrict__ pw_w) {
    int idx0 = blockIdx.x * blockDim.x + threadIdx.x;
    int stride = gridDim.x * blockDim.x;
    if (idx0 == 0) g_amax = 0;
    for (int idx = idx0; idx < 9 * C4; idx += stride) {
        int tap = idx >> 8, c = idx & 255;
        g_dwT[idx] = dw_w[c * 9 + tap];
    }
    for (int idx = idx0; idx < C4 * C4; idx += stride) {
        float v = pw_w[idx];
        bf16 h = __float2bfloat16(v);
        g_pw_hi[idx] = h;
        g_pw_lo[idx] = __float2bfloat16(v - __bfloat162float(h));
    }
}

// prep cv weights: per-oc scale + int8 hi/lo into swizzled tiles
__global__ void prep_cvq_kernel(const float* __restrict__ cv_w) {
    __shared__ float red[256];
    int oc = blockIdx.x, t = threadIdx.x;
    float m = 0.0f;
    #pragma unroll
    for (int tap = 0; tap < 9; tap++)
        m = fmaxf(m, fabsf(cv_w[((size_t)oc * C4 + t) * 9 + tap]));
    red[t] = m;
    __syncthreads();
    for (int o = 128; o > 0; o >>= 1) {
        if (t < o) red[t] = fmaxf(red[t], red[t + o]);
        __syncthreads();
    }
    float mx = red[0];
    float s = (mx > 0.0f) ? (mx / 127.0f) : 1.0f;
    if (t == 0) g_sW[oc] = s;
    float inv = 1.0f / s;
    int oh = oc >> 7, oc7 = oc & 127;
    int kb = t >> 5, ic5 = t & 31;
    #pragma unroll
    for (int tap = 0; tap < 9; tap++) {
        float u = cv_w[((size_t)oc * C4 + t) * 9 + tap] * inv;
        int qh = __float2int_rn(u);
        qh = max(-127, min(127, qh));
        int ql = __float2int_rn((u - (float)qh) * 127.0f);
        ql = max(-127, min(127, ql));
        size_t base = ((size_t)(tap * 8 + kb) * 2 + oh) * 4096;
        uint32_t a = packB(oc7, ic5);
        g_cvBh[base + a] = (char)qh;
        g_cvBl[base + a] = (char)ql;
    }
}

// ---------------------------------------------------------------------------
// DWT + transpose:  x (NCHW) -> t0 (fp32 NHWC)
// ---------------------------------------------------------------------------
__global__ void dwt_kernel(const float* __restrict__ x) {
    __shared__ float4 s[16][17];
    int b = blockIdx.z, j = blockIdx.y;
    int ctile = blockIdx.x >> 3, itile = blockIdx.x & 7;
    int tx = threadIdx.x, ty = threadIdx.y;

    int c = ctile * 16 + ty, i = itile * 16 + tx;
    const float* p = x + (((size_t)(b * CC + c) * 256) + 2 * j) * 256 + 2 * i;
    float2 top = *(const float2*)p;
    float2 bot = *(const float2*)(p + 256);
    float a = top.x, bq = top.y, cq = bot.x, d = bot.y;
    s[ty][tx] = make_float4((a + bq + cq + d) * 0.5f, (a + bq - cq - d) * 0.5f,
                            (a - bq + cq - d) * 0.5f, (a - bq - cq + d) * 0.5f);
    __syncthreads();
    float4 v = s[tx][ty];
    int c2 = ctile * 16 + tx, i2 = itile * 16 + ty;
    *(float4*)(g_t0 + ((((size_t)b * H2 + i2) * W2) + j) * C4 + 4 * c2) = v;
}

// ---------------------------------------------------------------------------
// Depthwise 3x3 + bias, split to bf16 hi/lo (pw input)
// ---------------------------------------------------------------------------
__global__ void dw_kernel(const float* __restrict__ dw_b) {
    int cq = threadIdx.x;
    int j = blockIdx.x * 4 + threadIdx.y;
    int i = blockIdx.y, b = blockIdx.z;
    int c0 = cq * 4;

    float4 acc = *(const float4*)(dw_b + c0);
    #pragma unroll
    for (int tap = 0; tap < 9; ++tap) {
        int ii = i + tap / 3 - 1, jj = j + tap % 3 - 1;
        if ((unsigned)ii < (unsigned)H2 && (unsigned)jj < (unsigned)W2) {
            float4 v = *(const float4*)(g_t0 + ((((size_t)b * H2 + ii) * W2) + jj) * C4 + c0);
            float4 w = *(const float4*)(g_dwT + tap * C4 + c0);
            acc.x += v.x * w.x; acc.y += v.y * w.y;
            acc.z += v.z * w.z; acc.w += v.w * w.w;
        }
    }
    size_t o = ((((size_t)b * H2 + i) * W2) + j) * C4 + c0;
    float vv[4] = {acc.x, acc.y, acc.z, acc.w};
    bf16 hb[4], lb[4];
    #pragma unroll
    for (int q = 0; q < 4; q++) {
        hb[q] = __float2bfloat16(vv[q]);
        lb[q] = __float2bfloat16(vv[q] - __bfloat162float(hb[q]));
    }
    *(uint2*)(g_a_hi + o) = *(uint2*)hb;
    *(uint2*)(g_a_lo + o) = *(uint2*)lb;
}

// ---------------------------------------------------------------------------
// pw GEMM (bf16 3-pass, proven structure). Out: g_t1 fp32 + global amax.
// ---------------------------------------------------------------------------
#define ROWP 80
#define A_T (128 * ROWP)
#define B_T (256 * ROWP)
#define STAGE_B (2 * A_T + 2 * B_T)
#define OFF_AH 0
#define OFF_AL A_T
#define OFF_BH (2 * A_T)
#define OFF_BL (2 * A_T + B_T)
#define NSTAGE 3
#define SMEM_PW (NSTAGE * STAGE_B)

__device__ __forceinline__ void pw_load_stage(uint32_t sb, int slot,
                                              int b, int i, int chunk, int t) {
    const int ic0 = chunk * 32;
    uint32_t st = sb + slot * STAGE_B;
    {
        int row = t >> 2, q = t & 3;
        size_t goff = (((size_t)b * H2 + i) * W2 + row) * (size_t)C4 + ic0 + q * 8;
        uint32_t dA = st + row * ROWP + q * 16;
        cpa16(dA + OFF_AH, g_a_hi + goff, true);
        cpa16(dA + OFF_AL, g_a_lo + goff, true);
    }
    #pragma unroll
    for (int rep = 0; rep < 2; rep++) {
        int sl = t + rep * 512;
        int row = sl >> 2, q = sl & 3;
        size_t w = (size_t)row * C4 + ic0 + q * 8;
        uint32_t dB = st + row * ROWP + q * 16;
        cpa16(dB + OFF_BH, g_pw_hi + w, true);
        cpa16(dB + OFF_BL, g_pw_lo + w, true);
    }
}

__global__ void __launch_bounds__(512, 1)
pw_gemm_kernel(const float* __restrict__ bias) {
    extern __shared__ char smem[];
    uint32_t sb = smem_to_u32(smem);
    const int t = threadIdx.x, lane = t & 31, wid = t >> 5;
    const int mw = wid & 3, nw = wid >> 2;
    const int bi = blockIdx.x;
    const int b = bi >> 7, i = bi & 127;

    float acc[2][8][4];
    #pragma unroll
    for (int tm = 0; tm < 2; tm++)
        #pragma unroll
        for (int tn = 0; tn < 8; tn++)
            #pragma unroll
            for (int q = 0; q < 4; q++) acc[tm][tn][q] = 0.0f;

    uint32_t aoff[2], boff[4];
    #pragma unroll
    for (int tm = 0; tm < 2; tm++)
        aoff[tm] = (mw * 32 + tm * 16 + (lane & 15)) * ROWP + (lane >> 4) * 16;
    #pragma unroll
    for (int g = 0; g < 4; g++)
        boff[g] = (nw * 64 + g * 16 + ((lane >> 4) & 1) * 8 + (lane & 7)) * ROWP
                + ((lane >> 3) & 1) * 16;

    pw_load_stage(sb, 0, b, i, 0, t); cpa_commit();
    pw_load_stage(sb, 1, b, i, 1, t); cpa_commit();

    int slot = 0;
    for (int c = 0; c < 8; c++) {
        cpa_wait<1>();
        __syncthreads();
        uint32_t st = sb + slot * STAGE_B;
        uint32_t Ahp = st + OFF_AH, Alp = st + OFF_AL;
        uint32_t Bhp = st + OFF_BH, Blp = st + OFF_BL;

        #pragma unroll
        for (int kh = 0; kh < 2; kh++) {
            uint32_t a_hi[2][4], a_lo[2][4], bf[4][4];
            #pragma unroll
            for (int tm = 0; tm < 2; tm++) ldsm4(a_hi[tm], Ahp + aoff[tm] + kh * 32);
            #pragma unroll
            for (int g = 0; g < 4; g++) ldsm4(bf[g], Bhp + boff[g] + kh * 32);
            #pragma unroll
            for (int tm = 0; tm < 2; tm++)
                #pragma unroll
                for (int g = 0; g < 4; g++) {
                    mma16816(acc[tm][2 * g],     a_hi[tm], bf[g][0], bf[g][1]);
                    mma16816(acc[tm][2 * g + 1], a_hi[tm], bf[g][2], bf[g][3]);
                }
            #pragma unroll
            for (int tm = 0; tm < 2; tm++) ldsm4(a_lo[tm], Alp + aoff[tm] + kh * 32);
            #pragma unroll
            for (int tm = 0; tm < 2; tm++)
                #pragma unroll
                for (int g = 0; g < 4; g++) {
                    mma16816(acc[tm][2 * g],     a_lo[tm], bf[g][0], bf[g][1]);
                    mma16816(acc[tm][2 * g + 1], a_lo[tm], bf[g][2], bf[g][3]);
                }
            #pragma unroll
            for (int g = 0; g < 4; g++) ldsm4(bf[g], Blp + boff[g] + kh * 32);
            #pragma unroll
            for (int tm = 0; tm < 2; tm++)
                #pragma unroll
                for (int g = 0; g < 4; g++) {
                    mma16816(acc[tm][2 * g],     a_hi[tm], bf[g][0], bf[g][1]);
                    mma16816(acc[tm][2 * g + 1], a_hi[tm], bf[g][2], bf[g][3]);
                }
        }
        if (c + 2 < 8) pw_load_stage(sb, (slot + 2) % NSTAGE, b, i, c + 2, t);
        cpa_commit();
        slot = (slot + 1) % NSTAGE;
    }

    // epilogue: fp32 out + amax
    float lmax = 0.0f;
    const int r = lane >> 2, cp = (lane & 3) * 2;
    #pragma unroll
    for (int tm = 0; tm < 2; tm++) {
        #pragma unroll
        for (int tn = 0; tn < 8; tn++) {
            int oc = nw * 64 + tn * 8 + cp;
            float bz0 = __ldg(bias + oc), bz1 = __ldg(bias + oc + 1);
            int j0 = mw * 32 + tm * 16 + r;
            #pragma unroll
            for (int half = 0; half < 2; half++) {
                int j = j0 + half * 8;
                float v0 = acc[tm][tn][half * 2 + 0] + bz0;
                float v1 = acc[tm][tn][half * 2 + 1] + bz1;
                lmax = fmaxf(lmax, fmaxf(fabsf(v0), fabsf(v1)));
                size_t off = ((((size_t)b * H2 + i) * W2) + j) * C4 + oc;
                *(float2*)(g_t1 + off) = make_float2(v0, v1);
            }
        }
    }
    #pragma unroll
    for (int o = 16; o > 0; o >>= 1)
        lmax = fmaxf(lmax, __shfl_xor_sync(0xFFFFFFFFu, lmax, o));
    if (lane == 0) atomicMax(&g_amax, __float_as_int(lmax));
}

// ---------------------------------------------------------------------------
// quantize pw output -> int8 hi/lo guarded A tiles for cv
// ---------------------------------------------------------------------------
__global__ void quant_kernel() {
    int cq = threadIdx.x;
    int j = blockIdx.x * 4 + threadIdx.y;
    int i = blockIdx.y, b = blockIdx.z;
    int c0 = cq * 4;
    float amax = __int_as_float(g_amax);
    float inv = (amax > 0.0f) ? (127.0f / amax) : 0.0f;
    float4 v = *(const float4*)(g_t1 + ((((size_t)b * H2 + i) * W2) + j) * C4 + c0);
    float u[4] = {v.x * inv, v.y * inv, v.z * inv, v.w * inv};
    char qh[4], ql[4];
    #pragma unroll
    for (int q = 0; q < 4; q++) {
        int h = __float2int_rn(u[q]);
        h = max(-127, min(127, h));
        int l = __float2int_rn((u[q] - (float)h) * 127.0f);
        l = max(-127, min(127, l));
        qh[q] = (char)h; ql[q] = (char)l;
    }
    int kb = c0 >> 5, ic5 = c0 & 31;
    size_t base = (((size_t)b * H2 + i) * 8 + kb) * ABLK + packA(j + 1, ic5);
    *(uint32_t*)(g_qah + base) = *(uint32_t*)qh;
    *(uint32_t*)(g_qal + base) = *(uint32_t*)ql;
}

// ---------------------------------------------------------------------------
// cv int8 IMMA GEMM: CTA 128(j) x 128(oc-half), bulk-copy 4-stage pipeline.
// acc = s_a*s_w*(hh + (lh + hl)/127); +bias, GELU -> g_t0 fp32 NHWC
// ---------------------------------------------------------------------------
#define CV_STG 16384
#define CV_NST 4
#define CV_SMEM (CV_NST * CV_STG + 64)

__device__ __forceinline__ void cv_issue(uint32_t sb, uint32_t mb,
                                         int b, int i, int oh, int c) {
    int s = c & 3;
    int tap = c >> 3, kb = c & 7;
    int di = tap / 3 - 1, dj = tap % 3 - 1;
    int ii = i + di;
    uint32_t dst = sb + s * CV_STG;
    const char *ah, *al;
    if ((unsigned)ii < (unsigned)H2) {
        size_t blk = (((size_t)b * H2 + ii) * 8 + kb) * ABLK + (size_t)(1 + dj) * 32;
        ah = g_qah + blk; al = g_qal + blk;
    } else {
        ah = g_zeroblk; al = g_zeroblk;
    }
    const char* bh = g_cvBh + ((size_t)(tap * 8 + kb) * 2 + oh) * 4096;
    const char* bl = g_cvBl + ((size_t)(tap * 8 + kb) * 2 + oh) * 4096;
    uint32_t mbar = mb + s * 8;
    MBARRIER_EXPECT_TX(mbar, 16384);
    bulk_g2s(dst,         ah, 4096, mbar);
    bulk_g2s(dst + 4096,  al, 4096, mbar);
    bulk_g2s(dst + 8192,  bh, 4096, mbar);
    bulk_g2s(dst + 12288, bl, 4096, mbar);
}

__global__ void __launch_bounds__(512, 1)
cv_imma_kernel(const float* __restrict__ bias) {
    extern __shared__ char smem[];
    uint32_t sb = smem_to_u32(smem);
    uint32_t mb = sb + CV_NST * CV_STG;
    const int t = threadIdx.x, lane = t & 31, wid = t >> 5;
    const int mw = wid & 3, nw = wid >> 2;   // 4(m) x 4(n), warp tile 32x32
    const int oh = blockIdx.x;
    const int bi = blockIdx.y;
    const int b = bi >> 7, i = bi & 127;

    if (t == 0) {
        #pragma unroll
        for (int s = 0; s < CV_NST; s++) MBARRIER_INIT(mb + s * 8, 1);
    }
    __syncthreads();
    if (t == 0) { cv_issue(sb, mb, b, i, oh, 0); cv_issue(sb, mb, b, i, oh, 1); cv_issue(sb, mb, b, i, oh, 2); }

    int acc_h[2][4][4], acc_m[2][4][4];
    #pragma unroll
    for (int tm = 0; tm < 2; tm++)
        #pragma unroll
        for (int tn = 0; tn < 4; tn++)
            #pragma unroll
            for (int q = 0; q < 4; q++) { acc_h[tm][tn][q] = 0; acc_m[tm][tn][q] = 0; }

    // ldmatrix row bases
    int a_row[2]; uint32_t a_r32[2];
    #pragma unroll
    for (int tm = 0; tm < 2; tm++) {
        a_row[tm] = mw * 32 + tm * 16 + (lane & 15);
        a_r32[tm] = (uint32_t)a_row[tm] * 32;
    }
    const int a_sb = lane >> 4;                  // 0/1 k-half
    uint32_t b_ad[2];
    #pragma unroll
    for (int g = 0; g < 2; g++) {
        int row = nw * 32 + g * 16 + ((lane >> 4) & 1) * 8 + (lane & 7);
        int bs = (lane >> 3) & 1;
        b_ad[g] = (uint32_t)row * 32 + (uint32_t)((bs ^ ((row >> 2) & 1)) << 4);
    }

    for (int c = 0; c < 72; c++) {
        int s = c & 3;
        MBARRIER_WAIT_PARITY(mb + s * 8, (c >> 2) & 1);
        __syncthreads();
        if (t == 0 && c + 3 < 72) cv_issue(sb, mb, b, i, oh, c + 3);

        int tap = c >> 3, dj = tap % 3 - 1;
        uint32_t st = sb + s * CV_STG;

        uint32_t A_h[2][4], A_l[2][4], Bf[2][4];
        #pragma unroll
        for (int tm = 0; tm < 2; tm++) {
            int f = ((a_row[tm] + 1 + dj) >> 2) & 1;
            uint32_t ad = a_r32[tm] + (uint32_t)((a_sb ^ f) << 4);
            ldsm4(A_h[tm], st + ad);
            ldsm4(A_l[tm], st + 4096 + ad);
        }
        #pragma unroll
        for (int g = 0; g < 2; g++) ldsm4(Bf[g], st + 8192 + b_ad[g]);
        #pragma unroll
        for (int tm = 0; tm < 2; tm++)
            #pragma unroll
            for (int g = 0; g < 2; g++) {
                imma16832(acc_h[tm][2 * g],     A_h[tm], Bf[g][0], Bf[g][1]);
                imma16832(acc_h[tm][2 * g + 1], A_h[tm], Bf[g][2], Bf[g][3]);
                imma16832(acc_m[tm][2 * g],     A_l[tm], Bf[g][0], Bf[g][1]);
                imma16832(acc_m[tm][2 * g + 1], A_l[tm], Bf[g][2], Bf[g][3]);
            }
        #pragma unroll
        for (int g = 0; g < 2; g++) ldsm4(Bf[g], st + 12288 + b_ad[g]);
        #pragma unroll
        for (int tm = 0; tm < 2; tm++)
            #pragma unroll
            for (int g = 0; g < 2; g++) {
                imma16832(acc_m[tm][2 * g],     A_h[tm], Bf[g][0], Bf[g][1]);
                imma16832(acc_m[tm][2 * g + 1], A_h[tm], Bf[g][2], Bf[g][3]);
            }
    }

    // epilogue
    float s_a = __int_as_float(g_amax) * (1.0f / 127.0f);
    const int r = lane >> 2, cp = (lane & 3) * 2;
    #pragma unroll
    for (int tm = 0; tm < 2; tm++) {
        #pragma unroll
        for (int tn = 0; tn < 4; tn++) {
            int oc = oh * 128 + nw * 32 + tn * 8 + cp;
            float f0 = s_a * g_sW[oc], f1 = s_a * g_sW[oc + 1];
            float bz0 = __ldg(bias + oc), bz1 = __ldg(bias + oc + 1);
            int j0 = mw * 32 + tm * 16 + r;
            #pragma unroll
            for (int half = 0; half < 2; half++) {
                int j = j0 + half * 8;
                float v0 = f0 * ((float)acc_h[tm][tn][half * 2 + 0]
                          + (float)acc_m[tm][tn][half * 2 + 0] * (1.0f / 127.0f)) + bz0;
                float v1 = f1 * ((float)acc_h[tm][tn][half * 2 + 1]
                          + (float)acc_m[tm][tn][half * 2 + 1] * (1.0f / 127.0f)) + bz1;
                size_t off = ((((size_t)b * H2 + i) * W2) + j) * C4 + oc;
                *(float2*)(g_t0 + off) = make_float2(gelu_exact(v0), gelu_exact(v1));
            }
        }
    }
}

// ---------------------------------------------------------------------------
// IDWT: t0 (fp32 NHWC) -> out (NCHW)
// ---------------------------------------------------------------------------
__global__ void idwt_kernel(float* __restrict__ out) {
    __shared__ float4 s[16][17];
    int b = blockIdx.z, h2 = blockIdx.y;
    int ctile = blockIdx.x >> 3, wtile = blockIdx.x & 7;
    int tx = threadIdx.x, ty = threadIdx.y;

    int c = ctile * 16 + tx, w2 = wtile * 16 + ty;
    s[ty][tx] = *(const float4*)(g_t0 + ((((size_t)b * H2 + w2) * W2) + h2) * C4 + 4 * c);
    __syncthreads();

    float4 v = s[tx][ty];
    int c2 = ctile * 16 + ty, w2b = wtile * 16 + tx;
    float ll = v.x, ch = v.y, cv = v.z, cd = v.w;
    float a  = (ll + ch + cv + cd) * 0.5f;
    float bq = (ll + ch - cv - cd) * 0.5f;
    float cq = (ll - ch + cv - cd) * 0.5f;
    float dq = (ll - ch - cv + cd) * 0.5f;
    float* o = out + (((size_t)(b * CC + c2) * 256) + 2 * h2) * 256 + 2 * w2b;
    *(float2*)o         = make_float2(a, bq);
    *(float2*)(o + 256) = make_float2(cq, dq);
}

// ---------------------------------------------------------------------------
extern "C" void kernel_launch(void* const* d_in, const int* in_sizes, int n_in,
                              void* d_out, int out_size) {
    const float* x    = (const float*)d_in[0];
    const float* dw_w = (const float*)d_in[1];
    const float* dw_b = (const float*)d_in[2];
    const float* pw_w = (const float*)d_in[3];
    const float* pw_b = (const float*)d_in[4];
    const float* cv_w = (const float*)d_in[5];
    const float* cv_b = (const float*)d_in[6];
    float* out = (float*)d_out;

    cudaFuncSetAttribute(pw_gemm_kernel,
                         cudaFuncAttributeMaxDynamicSharedMemorySize, SMEM_PW);
    cudaFuncSetAttribute(cv_imma_kernel,
                         cudaFuncAttributeMaxDynamicSharedMemorySize, CV_SMEM);

    prep_kernel<<<512, 256>>>(dw_w, pw_w);
    prep_cvq_kernel<<<256, 256>>>(cv_w);
    dwt_kernel<<<dim3(32, 128, BB), dim3(16, 16)>>>(x);
    dw_kernel<<<dim3(32, 128, BB), dim3(64, 4)>>>(dw_b);
    pw_gemm_kernel<<<1024, 512, SMEM_PW>>>(pw_b);
    quant_kernel<<<dim3(32, 128, BB), dim3(64, 4)>>>();
    cv_imma_kernel<<<dim3(2, 1024), 512, CV_SMEM>>>(cv_b);
    idwt_kernel<<<dim3(32, 128, BB), dim3(16, 16)>>>(out);
}

// round 7
// speedup vs baseline: 2.7259x; 2.7259x over previous
#include <cuda_runtime.h>
#include <cuda_bf16.h>
#include <math.h>
#include <stdint.h>

#define BB 8
#define CC 64
#define C4 256
#define H2 128
#define W2 128

typedef __nv_bfloat16 bf16;

// ---------------------------------------------------------------------------
// Tile geometry: byte-exact smem images, 80B-padded rows (proven conflict-free)
// ---------------------------------------------------------------------------
#define ROWP 80
#define A_T (128 * ROWP)            // 10240  A tile (128 rows)
#define AG_T (130 * ROWP)           // 10400  guarded A block (halo rows 0,129)
#define B_T (256 * ROWP)            // 20480  B tile (256 oc rows)
#define OFF_AH 0
#define OFF_AL A_T
#define OFF_BH (2 * A_T)
#define OFF_BL (2 * A_T + B_T)
#define STAGE_B (2 * A_T + 2 * B_T) // 61440
#define NSTAGE 3
#define SMEM_DYN (NSTAGE * STAGE_B + 64)

// ---------------------------------------------------------------------------
// Global scratch
// ---------------------------------------------------------------------------
__device__ float g_t0[(size_t)BB * H2 * W2 * C4];      // dwt out / cv out (fp32 NHWC)
__device__ float g_dwT[9 * C4];

// packed tiles (smem images)
__device__ char g_pwA_hi[(size_t)BB * H2 * 8 * A_T];   // [b*128+i][chunk]
__device__ char g_pwA_lo[(size_t)BB * H2 * 8 * A_T];
__device__ char g_pwB_hi[8 * B_T];                     // [chunk]
__device__ char g_pwB_lo[8 * B_T];
__device__ char g_cvA_hi[(size_t)BB * H2 * 8 * AG_T];  // [b*128+i][kb] guarded
__device__ char g_cvA_lo[(size_t)BB * H2 * 8 * AG_T];
__device__ char g_cvB_hi[72 * B_T];                    // [tap*8+kb]
__device__ char g_cvB_lo[72 * B_T];
__device__ char g_zeroA[AG_T];                         // never written -> zeros

__device__ __forceinline__ float gelu_exact(float v) {
    return 0.5f * v * (1.0f + erff(v * 0.70710678118654752f));
}
__device__ __forceinline__ uint32_t smem_to_u32(const void* p) {
    uint32_t a;
    asm("{ .reg .u64 t; cvta.to.shared.u64 t, %1; cvt.u32.u64 %0, t; }" : "=r"(a) : "l"(p));
    return a;
}

// ---- bulk copy + mbarrier ----
__device__ __forceinline__ void bulk_g2s(uint32_t dst, const void* src,
                                         uint32_t bytes, uint32_t mbar) {
    asm volatile(
        "cp.async.bulk.shared::cluster.global.mbarrier::complete_tx::bytes "
        "[%0], [%1], %2, [%3];"
        :: "r"(dst), "l"(src), "r"(bytes), "r"(mbar) : "memory");
}
#define MBARRIER_INIT(mbar, count) \
    asm volatile("mbarrier.init.shared.b64 [%0], %1;" :: "r"((uint32_t)(mbar)), "r"((uint32_t)(count)) : "memory")
#define MBARRIER_EXPECT_TX(mbar, bytes) \
    asm volatile("mbarrier.arrive.expect_tx.shared.b64 _, [%0], %1;" :: "r"((uint32_t)(mbar)), "r"((uint32_t)(bytes)) : "memory")
#define MBARRIER_WAIT_PARITY(mbar_smem_addr, phase_parity) do { \
    uint32_t _mbar = (uint32_t)(mbar_smem_addr); \
    uint32_t _parity = (uint32_t)(phase_parity); \
    uint32_t _done; \
    asm volatile("{\n\t.reg .pred p;\n\t" \
        "mbarrier.try_wait.parity.acquire.cta.shared::cta.b64 p, [%1], %2;\n\t" \
        "selp.b32 %0, 1, 0, p;\n\t}" : "=r"(_done) : "r"(_mbar), "r"(_parity) : "memory"); \
    if (!_done) { \
        asm volatile("{\n\t.reg .pred P1;\n\t" \
            "WAIT_LOOP_%=:\n\t" \
            "mbarrier.try_wait.parity.acquire.cta.shared::cta.b64 P1, [%0], %1, 0x989680;\n\t" \
            "@P1 bra.uni WAIT_DONE_%=;\n\t" \
            "bra.uni WAIT_LOOP_%=;\n\t" \
            "WAIT_DONE_%=:\n\t}" :: "r"(_mbar), "r"(_parity) : "memory"); \
    } \
} while(0)

// ---- mma ----
__device__ __forceinline__ void ldsm4(uint32_t* r, uint32_t addr) {
    asm volatile("ldmatrix.sync.aligned.m8n8.x4.shared.b16 {%0,%1,%2,%3}, [%4];"
                 : "=r"(r[0]), "=r"(r[1]), "=r"(r[2]), "=r"(r[3]) : "r"(addr));
}
__device__ __forceinline__ void mma16816(float* c, const uint32_t* a,
                                         uint32_t b0, uint32_t b1) {
    asm volatile(
        "mma.sync.aligned.m16n8k16.row.col.f32.bf16.bf16.f32 "
        "{%0,%1,%2,%3}, {%4,%5,%6,%7}, {%8,%9}, {%0,%1,%2,%3};"
        : "+f"(c[0]), "+f"(c[1]), "+f"(c[2]), "+f"(c[3])
        : "r"(a[0]), "r"(a[1]), "r"(a[2]), "r"(a[3]), "r"(b0), "r"(b1));
}

// ---------------------------------------------------------------------------
// prep: dw weights, pw/cv weight tiles (bf16 hi/lo, smem-image layout)
// ---------------------------------------------------------------------------
__global__ void prep_kernel(const float* __restrict__ dw_w,
                            const float* __restrict__ pw_w,
                            const float* __restrict__ cv_w) {
    int idx0 = blockIdx.x * blockDim.x + threadIdx.x;
    int stride = gridDim.x * blockDim.x;
    for (int idx = idx0; idx < 9 * C4; idx += stride) {
        int tap = idx >> 8, c = idx & 255;
        g_dwT[idx] = dw_w[c * 9 + tap];
    }
    for (int idx = idx0; idx < C4 * C4; idx += stride) {
        int oc = idx >> 8, ic = idx & 255;
        float v = pw_w[idx];                       // [oc][ic]
        bf16 h = __float2bfloat16(v);
        bf16 l = __float2bfloat16(v - __bfloat162float(h));
        size_t o = (size_t)(ic >> 5) * B_T + (size_t)oc * ROWP + (ic & 31) * 2;
        *(bf16*)(g_pwB_hi + o) = h;
        *(bf16*)(g_pwB_lo + o) = l;
    }
    for (int idx = idx0; idx < 9 * C4 * C4; idx += stride) {
        int tap = idx / (C4 * C4);
        int r = idx % (C4 * C4);
        int oc = r >> 8, ic = r & 255;
        float v = cv_w[((size_t)oc * C4 + ic) * 9 + tap];
        bf16 h = __float2bfloat16(v);
        bf16 l = __float2bfloat16(v - __bfloat162float(h));
        size_t o = (size_t)(tap * 8 + (ic >> 5)) * B_T + (size_t)oc * ROWP + (ic & 31) * 2;
        *(bf16*)(g_cvB_hi + o) = h;
        *(bf16*)(g_cvB_lo + o) = l;
    }
}

// ---------------------------------------------------------------------------
// DWT + transpose:  x (NCHW) -> t0 (fp32 NHWC)
// ---------------------------------------------------------------------------
__global__ void dwt_kernel(const float* __restrict__ x) {
    __shared__ float4 s[16][17];
    int b = blockIdx.z, j = blockIdx.y;
    int ctile = blockIdx.x >> 3, itile = blockIdx.x & 7;
    int tx = threadIdx.x, ty = threadIdx.y;

    int c = ctile * 16 + ty, i = itile * 16 + tx;
    const float* p = x + (((size_t)(b * CC + c) * 256) + 2 * j) * 256 + 2 * i;
    float2 top = *(const float2*)p;
    float2 bot = *(const float2*)(p + 256);
    float a = top.x, bq = top.y, cq = bot.x, d = bot.y;
    s[ty][tx] = make_float4((a + bq + cq + d) * 0.5f, (a + bq - cq - d) * 0.5f,
                            (a - bq + cq - d) * 0.5f, (a - bq - cq + d) * 0.5f);
    __syncthreads();
    float4 v = s[tx][ty];
    int c2 = ctile * 16 + tx, i2 = itile * 16 + ty;
    *(float4*)(g_t0 + ((((size_t)b * H2 + i2) * W2) + j) * C4 + 4 * c2) = v;
}

// ---------------------------------------------------------------------------
// Depthwise 3x3 + bias, split to bf16 hi/lo, write packed pw-A tiles
// ---------------------------------------------------------------------------
__global__ void dw_kernel(const float* __restrict__ dw_b) {
    int cq = threadIdx.x;
    int j = blockIdx.x * 4 + threadIdx.y;
    int i = blockIdx.y, b = blockIdx.z;
    int c0 = cq * 4;

    float4 acc = *(const float4*)(dw_b + c0);
    #pragma unroll
    for (int tap = 0; tap < 9; ++tap) {
        int ii = i + tap / 3 - 1, jj = j + tap % 3 - 1;
        if ((unsigned)ii < (unsigned)H2 && (unsigned)jj < (unsigned)W2) {
            float4 v = *(const float4*)(g_t0 + ((((size_t)b * H2 + ii) * W2) + jj) * C4 + c0);
            float4 w = *(const float4*)(g_dwT + tap * C4 + c0);
            acc.x += v.x * w.x; acc.y += v.y * w.y;
            acc.z += v.z * w.z; acc.w += v.w * w.w;
        }
    }
    float vv[4] = {acc.x, acc.y, acc.z, acc.w};
    bf16 hb[4], lb[4];
    #pragma unroll
    for (int q = 0; q < 4; q++) {
        hb[q] = __float2bfloat16(vv[q]);
        lb[q] = __float2bfloat16(vv[q] - __bfloat162float(hb[q]));
    }
    size_t o = (size_t)(((b * H2 + i) * 8) + (c0 >> 5)) * A_T
             + (size_t)j * ROWP + (c0 & 31) * 2;
    *(uint2*)(g_pwA_hi + o) = *(uint2*)hb;
    *(uint2*)(g_pwA_lo + o) = *(uint2*)lb;
}

// ---------------------------------------------------------------------------
// Unified bf16 3-pass HMMA GEMM. CTA: M=128(j) x N=256(oc), 512 thr, 4x4 warps.
// Loads: 4 cp.async.bulk per chunk, 3-stage mbarrier ring.
// IS_CV=false: pw (NC=8), out -> packed cv-A tiles (hi/lo, row j+1).
// IS_CV=true:  cv (NC=72), out -> g_t0 fp32 with bias+GELU.
// ---------------------------------------------------------------------------
template<bool IS_CV>
__device__ __forceinline__ void issue_chunk(uint32_t sb, uint32_t mb,
                                            int bi, int i, int c) {
    int s = c % NSTAGE;
    uint32_t st = sb + s * STAGE_B;
    const char *ah, *al, *bh, *bl;
    if (IS_CV) {
        int tap = c >> 3, kb = c & 7;
        int di = tap / 3 - 1, dj = tap % 3 - 1;
        int ii = i + di;
        if ((unsigned)ii < (unsigned)H2) {
            size_t blk = (size_t)(((bi & ~127) + ii) * 8 + kb) * AG_T + (size_t)(1 + dj) * ROWP;
            ah = g_cvA_hi + blk; al = g_cvA_lo + blk;
        } else {
            ah = g_zeroA; al = g_zeroA;
        }
        bh = g_cvB_hi + (size_t)c * B_T; bl = g_cvB_lo + (size_t)c * B_T;
    } else {
        size_t blk = (size_t)(bi * 8 + c) * A_T;
        ah = g_pwA_hi + blk; al = g_pwA_lo + blk;
        bh = g_pwB_hi + (size_t)c * B_T; bl = g_pwB_lo + (size_t)c * B_T;
    }
    uint32_t mbar = mb + s * 8;
    MBARRIER_EXPECT_TX(mbar, STAGE_B);
    bulk_g2s(st + OFF_AH, ah, A_T, mbar);
    bulk_g2s(st + OFF_AL, al, A_T, mbar);
    bulk_g2s(st + OFF_BH, bh, B_T, mbar);
    bulk_g2s(st + OFF_BL, bl, B_T, mbar);
}

template<int NC, bool IS_CV>
__global__ void __launch_bounds__(512, 1)
gemm_bulk_kernel(const float* __restrict__ bias) {
    extern __shared__ char smem[];
    uint32_t sb = smem_to_u32(smem);
    uint32_t mb = sb + NSTAGE * STAGE_B;
    const int t = threadIdx.x, lane = t & 31, wid = t >> 5;
    const int mw = wid & 3, nw = wid >> 2;
    const int bi = blockIdx.x;
    const int b = bi >> 7, i = bi & 127;

    if (t == 0) {
        #pragma unroll
        for (int s = 0; s < NSTAGE; s++) MBARRIER_INIT(mb + s * 8, 1);
    }
    __syncthreads();
    if (t == 0) {
        issue_chunk<IS_CV>(sb, mb, bi, i, 0);
        issue_chunk<IS_CV>(sb, mb, bi, i, 1);
    }

    float acc[2][8][4];
    #pragma unroll
    for (int tm = 0; tm < 2; tm++)
        #pragma unroll
        for (int tn = 0; tn < 8; tn++)
            #pragma unroll
            for (int q = 0; q < 4; q++) acc[tm][tn][q] = 0.0f;

    uint32_t aoff[2], boff[4];
    #pragma unroll
    for (int tm = 0; tm < 2; tm++)
        aoff[tm] = (mw * 32 + tm * 16 + (lane & 15)) * ROWP + (lane >> 4) * 16;
    #pragma unroll
    for (int g = 0; g < 4; g++)
        boff[g] = (nw * 64 + g * 16 + ((lane >> 4) & 1) * 8 + (lane & 7)) * ROWP
                + ((lane >> 3) & 1) * 16;

    int parity = 0;
    for (int c = 0; c < NC; c++) {
        int s = c % NSTAGE;
        MBARRIER_WAIT_PARITY(mb + s * 8, parity);
        if (s == NSTAGE - 1) parity ^= 1;
        __syncthreads();
        // stage (c+2)%3 was consumed at chunk c-1; all threads are past it.
        if (t == 0 && c + 2 < NC) issue_chunk<IS_CV>(sb, mb, bi, i, c + 2);

        uint32_t st = sb + s * STAGE_B;
        uint32_t Ahp = st + OFF_AH, Alp = st + OFF_AL;
        uint32_t Bhp = st + OFF_BH, Blp = st + OFF_BL;

        #pragma unroll
        for (int kh = 0; kh < 2; kh++) {
            uint32_t a_hi[2][4], a_lo[2][4], bf[4][4];
            #pragma unroll
            for (int tm = 0; tm < 2; tm++) ldsm4(a_hi[tm], Ahp + aoff[tm] + kh * 32);
            #pragma unroll
            for (int g = 0; g < 4; g++) ldsm4(bf[g], Bhp + boff[g] + kh * 32);
            #pragma unroll
            for (int tm = 0; tm < 2; tm++)
                #pragma unroll
                for (int g = 0; g < 4; g++) {
                    mma16816(acc[tm][2 * g],     a_hi[tm], bf[g][0], bf[g][1]);
                    mma16816(acc[tm][2 * g + 1], a_hi[tm], bf[g][2], bf[g][3]);
                }
            #pragma unroll
            for (int tm = 0; tm < 2; tm++) ldsm4(a_lo[tm], Alp + aoff[tm] + kh * 32);
            #pragma unroll
            for (int tm = 0; tm < 2; tm++)
                #pragma unroll
                for (int g = 0; g < 4; g++) {
                    mma16816(acc[tm][2 * g],     a_lo[tm], bf[g][0], bf[g][1]);
                    mma16816(acc[tm][2 * g + 1], a_lo[tm], bf[g][2], bf[g][3]);
                }
            #pragma unroll
            for (int g = 0; g < 4; g++) ldsm4(bf[g], Blp + boff[g] + kh * 32);
            #pragma unroll
            for (int tm = 0; tm < 2; tm++)
                #pragma unroll
                for (int g = 0; g < 4; g++) {
                    mma16816(acc[tm][2 * g],     a_hi[tm], bf[g][0], bf[g][1]);
                    mma16816(acc[tm][2 * g + 1], a_hi[tm], bf[g][2], bf[g][3]);
                }
        }
    }

    // Epilogue
    const int r = lane >> 2, cp = (lane & 3) * 2;
    #pragma unroll
    for (int tm = 0; tm < 2; tm++) {
        #pragma unroll
        for (int tn = 0; tn < 8; tn++) {
            int oc = nw * 64 + tn * 8 + cp;
            float bz0 = __ldg(bias + oc), bz1 = __ldg(bias + oc + 1);
            int j0 = mw * 32 + tm * 16 + r;
            #pragma unroll
            for (int half = 0; half < 2; half++) {
                int j = j0 + half * 8;
                float v0 = acc[tm][tn][half * 2 + 0] + bz0;
                float v1 = acc[tm][tn][half * 2 + 1] + bz1;
                if (IS_CV) {
                    size_t off = ((((size_t)b * H2 + i) * W2) + j) * C4 + oc;
                    *(float2*)(g_t0 + off) = make_float2(gelu_exact(v0), gelu_exact(v1));
                } else {
                    bf16 h0 = __float2bfloat16(v0);
                    bf16 h1 = __float2bfloat16(v1);
                    bf16 l0 = __float2bfloat16(v0 - __bfloat162float(h0));
                    bf16 l1 = __float2bfloat16(v1 - __bfloat162float(h1));
                    bf16 hp[2] = {h0, h1};
                    bf16 lp[2] = {l0, l1};
                    size_t o = (size_t)((bi * 8) + (oc >> 5)) * AG_T
                             + (size_t)(j + 1) * ROWP + (oc & 31) * 2;
                    *(uint32_t*)(g_cvA_hi + o) = *(uint32_t*)hp;
                    *(uint32_t*)(g_cvA_lo + o) = *(uint32_t*)lp;
                }
            }
        }
    }
}

// ---------------------------------------------------------------------------
// IDWT: t0 (fp32 NHWC) -> out (NCHW)
// ---------------------------------------------------------------------------
__global__ void idwt_kernel(float* __restrict__ out) {
    __shared__ float4 s[16][17];
    int b = blockIdx.z, h2 = blockIdx.y;
    int ctile = blockIdx.x >> 3, wtile = blockIdx.x & 7;
    int tx = threadIdx.x, ty = threadIdx.y;

    int c = ctile * 16 + tx, w2 = wtile * 16 + ty;
    s[ty][tx] = *(const float4*)(g_t0 + ((((size_t)b * H2 + w2) * W2) + h2) * C4 + 4 * c);
    __syncthreads();

    float4 v = s[tx][ty];
    int c2 = ctile * 16 + ty, w2b = wtile * 16 + tx;
    float ll = v.x, ch = v.y, cv = v.z, cd = v.w;
    float a  = (ll + ch + cv + cd) * 0.5f;
    float bq = (ll + ch - cv - cd) * 0.5f;
    float cq = (ll - ch + cv - cd) * 0.5f;
    float dq = (ll - ch - cv + cd) * 0.5f;
    float* o = out + (((size_t)(b * CC + c2) * 256) + 2 * h2) * 256 + 2 * w2b;
    *(float2*)o         = make_float2(a, bq);
    *(float2*)(o + 256) = make_float2(cq, dq);
}

// ---------------------------------------------------------------------------
extern "C" void kernel_launch(void* const* d_in, const int* in_sizes, int n_in,
                              void* d_out, int out_size) {
    const float* x    = (const float*)d_in[0];
    const float* dw_w = (const float*)d_in[1];
    const float* dw_b = (const float*)d_in[2];
    const float* pw_w = (const float*)d_in[3];
    const float* pw_b = (const float*)d_in[4];
    const float* cv_w = (const float*)d_in[5];
    const float* cv_b = (const float*)d_in[6];
    float* out = (float*)d_out;

    cudaFuncSetAttribute(gemm_bulk_kernel<8, false>,
                         cudaFuncAttributeMaxDynamicSharedMemorySize, SMEM_DYN);
    cudaFuncSetAttribute(gemm_bulk_kernel<72, true>,
                         cudaFuncAttributeMaxDynamicSharedMemorySize, SMEM_DYN);

    prep_kernel<<<1024, 256>>>(dw_w, pw_w, cv_w);
    dwt_kernel<<<dim3(32, 128, BB), dim3(16, 16)>>>(x);
    dw_kernel<<<dim3(32, 128, BB), dim3(64, 4)>>>(dw_b);
    gemm_bulk_kernel<8, false><<<1024, 512, SMEM_DYN>>>(pw_b);
    gemm_bulk_kernel<72, true><<<1024, 512, SMEM_DYN>>>(cv_b);
    idwt_kernel<<<dim3(32, 128, BB), dim3(16, 16)>>>(out);
}

// round 8
// speedup vs baseline: 2.8057x; 1.0293x over previous
#include <cuda_runtime.h>
#include <cuda_bf16.h>
#include <math.h>
#include <stdint.h>

#define BB 8
#define CC 64
#define C4 256
#define H2 128
#define W2 128

typedef __nv_bfloat16 bf16;

// ---------------------------------------------------------------------------
// Tile geometry: byte-exact smem images, 80B-padded rows
// ---------------------------------------------------------------------------
#define ROWP 80
#define A_T (128 * ROWP)            // 10240  A tile (128 j-rows)
#define AG_T (130 * ROWP)           // 10400  guarded A block (halo rows 0,129)
#define B_T (128 * ROWP)            // 10240  B tile (128 oc rows = one half)
#define OFF_AH 0
#define OFF_AL A_T
#define OFF_BH (2 * A_T)
#define OFF_BL (2 * A_T + B_T)
#define STAGE_B (2 * A_T + 2 * B_T) // 40960
#define NSTAGE 2
#define SMEM_DYN (NSTAGE * STAGE_B + 64)   // 81984 -> 2 CTAs/SM

// ---------------------------------------------------------------------------
// Global scratch
// ---------------------------------------------------------------------------
__device__ float g_t0[(size_t)BB * H2 * W2 * C4];      // dwt out / cv out (fp32 NHWC)
__device__ float g_dwT[9 * C4];

// packed tiles (smem images)
__device__ char g_pwA_hi[(size_t)BB * H2 * 8 * A_T];   // [b*128+i][chunk]
__device__ char g_pwA_lo[(size_t)BB * H2 * 8 * A_T];
__device__ char g_pwB_hi[8 * 2 * B_T];                 // [chunk][ochalf]
__device__ char g_pwB_lo[8 * 2 * B_T];
__device__ char g_cvA_hi[(size_t)BB * H2 * 8 * AG_T];  // [b*128+i][kb] guarded
__device__ char g_cvA_lo[(size_t)BB * H2 * 8 * AG_T];
__device__ char g_cvB_hi[72 * 2 * B_T];                // [tap*8+kb][ochalf]
__device__ char g_cvB_lo[72 * 2 * B_T];
__device__ char g_zeroA[AG_T];                         // never written -> zeros

__device__ __forceinline__ float gelu_exact(float v) {
    return 0.5f * v * (1.0f + erff(v * 0.70710678118654752f));
}
__device__ __forceinline__ uint32_t smem_to_u32(const void* p) {
    uint32_t a;
    asm("{ .reg .u64 t; cvta.to.shared.u64 t, %1; cvt.u32.u64 %0, t; }" : "=r"(a) : "l"(p));
    return a;
}

// ---- bulk copy + mbarrier ----
__device__ __forceinline__ void bulk_g2s(uint32_t dst, const void* src,
                                         uint32_t bytes, uint32_t mbar) {
    asm volatile(
        "cp.async.bulk.shared::cluster.global.mbarrier::complete_tx::bytes "
        "[%0], [%1], %2, [%3];"
        :: "r"(dst), "l"(src), "r"(bytes), "r"(mbar) : "memory");
}
#define MBARRIER_INIT(mbar, count) \
    asm volatile("mbarrier.init.shared.b64 [%0], %1;" :: "r"((uint32_t)(mbar)), "r"((uint32_t)(count)) : "memory")
#define MBARRIER_EXPECT_TX(mbar, bytes) \
    asm volatile("mbarrier.arrive.expect_tx.shared.b64 _, [%0], %1;" :: "r"((uint32_t)(mbar)), "r"((uint32_t)(bytes)) : "memory")
#define MBARRIER_WAIT_PARITY(mbar_smem_addr, phase_parity) do { \
    uint32_t _mbar = (uint32_t)(mbar_smem_addr); \
    uint32_t _parity = (uint32_t)(phase_parity); \
    uint32_t _done; \
    asm volatile("{\n\t.reg .pred p;\n\t" \
        "mbarrier.try_wait.parity.acquire.cta.shared::cta.b64 p, [%1], %2;\n\t" \
        "selp.b32 %0, 1, 0, p;\n\t}" : "=r"(_done) : "r"(_mbar), "r"(_parity) : "memory"); \
    if (!_done) { \
        asm volatile("{\n\t.reg .pred P1;\n\t" \
            "WAIT_LOOP_%=:\n\t" \
            "mbarrier.try_wait.parity.acquire.cta.shared::cta.b64 P1, [%0], %1, 0x989680;\n\t" \
            "@P1 bra.uni WAIT_DONE_%=;\n\t" \
            "bra.uni WAIT_LOOP_%=;\n\t" \
            "WAIT_DONE_%=:\n\t}" :: "r"(_mbar), "r"(_parity) : "memory"); \
    } \
} while(0)

// ---- mma ----
__device__ __forceinline__ void ldsm4(uint32_t* r, uint32_t addr) {
    asm volatile("ldmatrix.sync.aligned.m8n8.x4.shared.b16 {%0,%1,%2,%3}, [%4];"
                 : "=r"(r[0]), "=r"(r[1]), "=r"(r[2]), "=r"(r[3]) : "r"(addr));
}
__device__ __forceinline__ void mma16816(float* c, const uint32_t* a,
                                         uint32_t b0, uint32_t b1) {
    asm volatile(
        "mma.sync.aligned.m16n8k16.row.col.f32.bf16.bf16.f32 "
        "{%0,%1,%2,%3}, {%4,%5,%6,%7}, {%8,%9}, {%0,%1,%2,%3};"
        : "+f"(c[0]), "+f"(c[1]), "+f"(c[2]), "+f"(c[3])
        : "r"(a[0]), "r"(a[1]), "r"(a[2]), "r"(a[3]), "r"(b0), "r"(b1));
}

// ---------------------------------------------------------------------------
// prep: dw weights, pw/cv weight tiles (bf16 hi/lo, smem-image, per oc-half)
// ---------------------------------------------------------------------------
__global__ void prep_kernel(const float* __restrict__ dw_w,
                            const float* __restrict__ pw_w,
                            const float* __restrict__ cv_w) {
    int idx0 = blockIdx.x * blockDim.x + threadIdx.x;
    int stride = gridDim.x * blockDim.x;
    for (int idx = idx0; idx < 9 * C4; idx += stride) {
        int tap = idx >> 8, c = idx & 255;
        g_dwT[idx] = dw_w[c * 9 + tap];
    }
    for (int idx = idx0; idx < C4 * C4; idx += stride) {
        int oc = idx >> 8, ic = idx & 255;
        float v = pw_w[idx];                       // [oc][ic]
        bf16 h = __float2bfloat16(v);
        bf16 l = __float2bfloat16(v - __bfloat162float(h));
        size_t o = (size_t)((ic >> 5) * 2 + (oc >> 7)) * B_T
                 + (size_t)(oc & 127) * ROWP + (ic & 31) * 2;
        *(bf16*)(g_pwB_hi + o) = h;
        *(bf16*)(g_pwB_lo + o) = l;
    }
    for (int idx = idx0; idx < 9 * C4 * C4; idx += stride) {
        int tap = idx / (C4 * C4);
        int r = idx % (C4 * C4);
        int oc = r >> 8, ic = r & 255;
        float v = cv_w[((size_t)oc * C4 + ic) * 9 + tap];
        bf16 h = __float2bfloat16(v);
        bf16 l = __float2bfloat16(v - __bfloat162float(h));
        size_t o = (size_t)((tap * 8 + (ic >> 5)) * 2 + (oc >> 7)) * B_T
                 + (size_t)(oc & 127) * ROWP + (ic & 31) * 2;
        *(bf16*)(g_cvB_hi + o) = h;
        *(bf16*)(g_cvB_lo + o) = l;
    }
}

// ---------------------------------------------------------------------------
// DWT + transpose:  x (NCHW) -> t0 (fp32 NHWC)
// ---------------------------------------------------------------------------
__global__ void dwt_kernel(const float* __restrict__ x) {
    __shared__ float4 s[16][17];
    int b = blockIdx.z, j = blockIdx.y;
    int ctile = blockIdx.x >> 3, itile = blockIdx.x & 7;
    int tx = threadIdx.x, ty = threadIdx.y;

    int c = ctile * 16 + ty, i = itile * 16 + tx;
    const float* p = x + (((size_t)(b * CC + c) * 256) + 2 * j) * 256 + 2 * i;
    float2 top = *(const float2*)p;
    float2 bot = *(const float2*)(p + 256);
    float a = top.x, bq = top.y, cq = bot.x, d = bot.y;
    s[ty][tx] = make_float4((a + bq + cq + d) * 0.5f, (a + bq - cq - d) * 0.5f,
                            (a - bq + cq - d) * 0.5f, (a - bq - cq + d) * 0.5f);
    __syncthreads();
    float4 v = s[tx][ty];
    int c2 = ctile * 16 + tx, i2 = itile * 16 + ty;
    *(float4*)(g_t0 + ((((size_t)b * H2 + i2) * W2) + j) * C4 + 4 * c2) = v;
}

// ---------------------------------------------------------------------------
// Depthwise 3x3 + bias, split to bf16 hi/lo, write packed pw-A tiles
// ---------------------------------------------------------------------------
__global__ void dw_kernel(const float* __restrict__ dw_b) {
    int cq = threadIdx.x;
    int j = blockIdx.x * 4 + threadIdx.y;
    int i = blockIdx.y, b = blockIdx.z;
    int c0 = cq * 4;

    float4 acc = *(const float4*)(dw_b + c0);
    #pragma unroll
    for (int tap = 0; tap < 9; ++tap) {
        int ii = i + tap / 3 - 1, jj = j + tap % 3 - 1;
        if ((unsigned)ii < (unsigned)H2 && (unsigned)jj < (unsigned)W2) {
            float4 v = *(const float4*)(g_t0 + ((((size_t)b * H2 + ii) * W2) + jj) * C4 + c0);
            float4 w = *(const float4*)(g_dwT + tap * C4 + c0);
            acc.x += v.x * w.x; acc.y += v.y * w.y;
            acc.z += v.z * w.z; acc.w += v.w * w.w;
        }
    }
    float vv[4] = {acc.x, acc.y, acc.z, acc.w};
    bf16 hb[4], lb[4];
    #pragma unroll
    for (int q = 0; q < 4; q++) {
        hb[q] = __float2bfloat16(vv[q]);
        lb[q] = __float2bfloat16(vv[q] - __bfloat162float(hb[q]));
    }
    size_t o = (size_t)(((b * H2 + i) * 8) + (c0 >> 5)) * A_T
             + (size_t)j * ROWP + (c0 & 31) * 2;
    *(uint2*)(g_pwA_hi + o) = *(uint2*)hb;
    *(uint2*)(g_pwA_lo + o) = *(uint2*)lb;
}

// ---------------------------------------------------------------------------
// Unified bf16 3-pass HMMA GEMM. CTA: M=128(j) x N=128(oc-half), 256 thr,
// warp grid 4(m)x2(n), 2-stage bulk ring, 2 CTAs/SM.
// IS_CV=false: pw (NC=8), out -> packed cv-A tiles (hi/lo, row j+1).
// IS_CV=true:  cv (NC=72), out -> g_t0 fp32 with bias+GELU.
// ---------------------------------------------------------------------------
template<bool IS_CV>
__device__ __forceinline__ void issue_chunk(uint32_t sb, uint32_t mb,
                                            int bi, int i, int oh, int c) {
    int s = c & 1;
    uint32_t st = sb + s * STAGE_B;
    const char *ah, *al, *bh, *bl;
    if (IS_CV) {
        int tap = c >> 3, kb = c & 7;
        int di = tap / 3 - 1, dj = tap % 3 - 1;
        int ii = i + di;
        if ((unsigned)ii < (unsigned)H2) {
            size_t blk = (size_t)(((bi & ~127) + ii) * 8 + kb) * AG_T + (size_t)(1 + dj) * ROWP;
            ah = g_cvA_hi + blk; al = g_cvA_lo + blk;
        } else {
            ah = g_zeroA; al = g_zeroA;
        }
        bh = g_cvB_hi + (size_t)(c * 2 + oh) * B_T;
        bl = g_cvB_lo + (size_t)(c * 2 + oh) * B_T;
    } else {
        size_t blk = (size_t)(bi * 8 + c) * A_T;
        ah = g_pwA_hi + blk; al = g_pwA_lo + blk;
        bh = g_pwB_hi + (size_t)(c * 2 + oh) * B_T;
        bl = g_pwB_lo + (size_t)(c * 2 + oh) * B_T;
    }
    uint32_t mbar = mb + s * 8;
    MBARRIER_EXPECT_TX(mbar, STAGE_B);
    bulk_g2s(st + OFF_AH, ah, A_T, mbar);
    bulk_g2s(st + OFF_AL, al, A_T, mbar);
    bulk_g2s(st + OFF_BH, bh, B_T, mbar);
    bulk_g2s(st + OFF_BL, bl, B_T, mbar);
}

template<int NC, bool IS_CV>
__global__ void __launch_bounds__(256, 2)
gemm_bulk_kernel(const float* __restrict__ bias) {
    extern __shared__ char smem[];
    uint32_t sb = smem_to_u32(smem);
    uint32_t mb = sb + NSTAGE * STAGE_B;
    const int t = threadIdx.x, lane = t & 31, wid = t >> 5;
    const int mw = wid & 3, nw = wid >> 2;     // 4(m) x 2(n), warp tile 32x64
    const int bi = blockIdx.x;
    const int oh = blockIdx.y;                 // oc half
    const int b = bi >> 7, i = bi & 127;

    if (t == 0) {
        MBARRIER_INIT(mb, 1);
        MBARRIER_INIT(mb + 8, 1);
    }
    __syncthreads();
    if (t == 0) {
        issue_chunk<IS_CV>(sb, mb, bi, i, oh, 0);
        issue_chunk<IS_CV>(sb, mb, bi, i, oh, 1);
    }

    float acc[2][8][4];
    #pragma unroll
    for (int tm = 0; tm < 2; tm++)
        #pragma unroll
        for (int tn = 0; tn < 8; tn++)
            #pragma unroll
            for (int q = 0; q < 4; q++) acc[tm][tn][q] = 0.0f;

    uint32_t aoff[2], boff[4];
    #pragma unroll
    for (int tm = 0; tm < 2; tm++)
        aoff[tm] = (mw * 32 + tm * 16 + (lane & 15)) * ROWP + (lane >> 4) * 16;
    #pragma unroll
    for (int g = 0; g < 4; g++)
        boff[g] = (nw * 64 + g * 16 + ((lane >> 4) & 1) * 8 + (lane & 7)) * ROWP
                + ((lane >> 3) & 1) * 16;

    for (int c = 0; c < NC; c++) {
        int s = c & 1;
        MBARRIER_WAIT_PARITY(mb + s * 8, (c >> 1) & 1);
        __syncthreads();

        uint32_t st = sb + s * STAGE_B;
        uint32_t Ahp = st + OFF_AH, Alp = st + OFF_AL;
        uint32_t Bhp = st + OFF_BH, Blp = st + OFF_BL;

        #pragma unroll
        for (int kh = 0; kh < 2; kh++) {
            uint32_t a_hi[2][4], a_lo[2][4], bf[4][4];
            #pragma unroll
            for (int tm = 0; tm < 2; tm++) ldsm4(a_hi[tm], Ahp + aoff[tm] + kh * 32);
            #pragma unroll
            for (int g = 0; g < 4; g++) ldsm4(bf[g], Bhp + boff[g] + kh * 32);
            #pragma unroll
            for (int tm = 0; tm < 2; tm++)
                #pragma unroll
                for (int g = 0; g < 4; g++) {
                    mma16816(acc[tm][2 * g],     a_hi[tm], bf[g][0], bf[g][1]);
                    mma16816(acc[tm][2 * g + 1], a_hi[tm], bf[g][2], bf[g][3]);
                }
            #pragma unroll
            for (int tm = 0; tm < 2; tm++) ldsm4(a_lo[tm], Alp + aoff[tm] + kh * 32);
            #pragma unroll
            for (int tm = 0; tm < 2; tm++)
                #pragma unroll
                for (int g = 0; g < 4; g++) {
                    mma16816(acc[tm][2 * g],     a_lo[tm], bf[g][0], bf[g][1]);
                    mma16816(acc[tm][2 * g + 1], a_lo[tm], bf[g][2], bf[g][3]);
                }
            #pragma unroll
            for (int g = 0; g < 4; g++) ldsm4(bf[g], Blp + boff[g] + kh * 32);
            #pragma unroll
            for (int tm = 0; tm < 2; tm++)
                #pragma unroll
                for (int g = 0; g < 4; g++) {
                    mma16816(acc[tm][2 * g],     a_hi[tm], bf[g][0], bf[g][1]);
                    mma16816(acc[tm][2 * g + 1], a_hi[tm], bf[g][2], bf[g][3]);
                }
        }

        // slot s is free only after every warp finished reading it
        __syncthreads();
        if (t == 0 && c + 2 < NC) issue_chunk<IS_CV>(sb, mb, bi, i, oh, c + 2);
    }

    // Epilogue
    const int r = lane >> 2, cp = (lane & 3) * 2;
    #pragma unroll
    for (int tm = 0; tm < 2; tm++) {
        #pragma unroll
        for (int tn = 0; tn < 8; tn++) {
            int oc = oh * 128 + nw * 64 + tn * 8 + cp;
            float bz0 = __ldg(bias + oc), bz1 = __ldg(bias + oc + 1);
            int j0 = mw * 32 + tm * 16 + r;
            #pragma unroll
            for (int half = 0; half < 2; half++) {
                int j = j0 + half * 8;
                float v0 = acc[tm][tn][half * 2 + 0] + bz0;
                float v1 = acc[tm][tn][half * 2 + 1] + bz1;
                if (IS_CV) {
                    size_t off = ((((size_t)b * H2 + i) * W2) + j) * C4 + oc;
                    *(float2*)(g_t0 + off) = make_float2(gelu_exact(v0), gelu_exact(v1));
                } else {
                    bf16 h0 = __float2bfloat16(v0);
                    bf16 h1 = __float2bfloat16(v1);
                    bf16 l0 = __float2bfloat16(v0 - __bfloat162float(h0));
                    bf16 l1 = __float2bfloat16(v1 - __bfloat162float(h1));
                    bf16 hp[2] = {h0, h1};
                    bf16 lp[2] = {l0, l1};
                    size_t o = (size_t)((bi * 8) + (oc >> 5)) * AG_T
                             + (size_t)(j + 1) * ROWP + (oc & 31) * 2;
                    *(uint32_t*)(g_cvA_hi + o) = *(uint32_t*)hp;
                    *(uint32_t*)(g_cvA_lo + o) = *(uint32_t*)lp;
                }
            }
        }
    }
}

// ---------------------------------------------------------------------------
// IDWT: t0 (fp32 NHWC) -> out (NCHW)
// ---------------------------------------------------------------------------
__global__ void idwt_kernel(float* __restrict__ out) {
    __shared__ float4 s[16][17];
    int b = blockIdx.z, h2 = blockIdx.y;
    int ctile = blockIdx.x >> 3, wtile = blockIdx.x & 7;
    int tx = threadIdx.x, ty = threadIdx.y;

    int c = ctile * 16 + tx, w2 = wtile * 16 + ty;
    s[ty][tx] = *(const float4*)(g_t0 + ((((size_t)b * H2 + w2) * W2) + h2) * C4 + 4 * c);
    __syncthreads();

    float4 v = s[tx][ty];
    int c2 = ctile * 16 + ty, w2b = wtile * 16 + tx;
    float ll = v.x, ch = v.y, cv = v.z, cd = v.w;
    float a  = (ll + ch + cv + cd) * 0.5f;
    float bq = (ll + ch - cv - cd) * 0.5f;
    float cq = (ll - ch + cv - cd) * 0.5f;
    float dq = (ll - ch - cv + cd) * 0.5f;
    float* o = out + (((size_t)(b * CC + c2) * 256) + 2 * h2) * 256 + 2 * w2b;
    *(float2*)o         = make_float2(a, bq);
    *(float2*)(o + 256) = make_float2(cq, dq);
}

// ---------------------------------------------------------------------------
extern "C" void kernel_launch(void* const* d_in, const int* in_sizes, int n_in,
                              void* d_out, int out_size) {
    const float* x    = (const float*)d_in[0];
    const float* dw_w = (const float*)d_in[1];
    const float* dw_b = (const float*)d_in[2];
    const float* pw_w = (const float*)d_in[3];
    const float* pw_b = (const float*)d_in[4];
    const float* cv_w = (const float*)d_in[5];
    const float* cv_b = (const float*)d_in[6];
    float* out = (float*)d_out;

    cudaFuncSetAttribute(gemm_bulk_kernel<8, false>,
                         cudaFuncAttributeMaxDynamicSharedMemorySize, SMEM_DYN);
    cudaFuncSetAttribute(gemm_bulk_kernel<72, true>,
                         cudaFuncAttributeMaxDynamicSharedMemorySize, SMEM_DYN);

    prep_kernel<<<1024, 256>>>(dw_w, pw_w, cv_w);
    dwt_kernel<<<dim3(32, 128, BB), dim3(16, 16)>>>(x);
    dw_kernel<<<dim3(32, 128, BB), dim3(64, 4)>>>(dw_b);
    gemm_bulk_kernel<8, false><<<dim3(1024, 2), 256, SMEM_DYN>>>(pw_b);
    gemm_bulk_kernel<72, true><<<dim3(1024, 2), 256, SMEM_DYN>>>(cv_b);
    idwt_kernel<<<dim3(32, 128, BB), dim3(16, 16)>>>(out);
}

// round 9
// speedup vs baseline: 3.7100x; 1.3223x over previous
#include <cuda_runtime.h>
#include <cuda_fp16.h>
#include <math.h>
#include <stdint.h>

#define BB 8
#define CC 64
#define C4 256
#define H2 128
#define W2 128

// ---------------------------------------------------------------------------
// Tile geometry: byte-exact smem images, 80B-padded rows (fp16: 32 k-elems=64B)
// ---------------------------------------------------------------------------
#define ROWP 80
#define A_T (128 * ROWP)            // 10240  A tile (128 j-rows)
#define AG_T (130 * ROWP)           // 10400  guarded A block (halo rows 0,129)
#define B_T (128 * ROWP)            // 10240  B tile (128 oc rows = one half)
#define OFF_AH 0
#define OFF_AL A_T
#define OFF_B  (2 * A_T)
#define STAGE_B (2 * A_T + B_T)     // 30720
#define NSTAGE 3
#define SMEM_DYN (NSTAGE * STAGE_B + 64)   // 92224 -> 2 CTAs/SM

// ---------------------------------------------------------------------------
// Global scratch
// ---------------------------------------------------------------------------
__device__ float g_t0[(size_t)BB * H2 * W2 * C4];      // dwt out / cv out (fp32 NHWC)
__device__ float g_dwT[9 * C4];

// packed tiles (smem images), fp16
__device__ __align__(128) char g_pwA_hi[(size_t)BB * H2 * 8 * A_T];   // [b*128+i][chunk]
__device__ __align__(128) char g_pwA_lo[(size_t)BB * H2 * 8 * A_T];
__device__ __align__(128) char g_pwB[8 * 2 * B_T];                    // [chunk][ochalf]
__device__ __align__(128) char g_cvA_hi[(size_t)BB * H2 * 8 * AG_T];  // [b*128+i][kb] guarded
__device__ __align__(128) char g_cvA_lo[(size_t)BB * H2 * 8 * AG_T];
__device__ __align__(128) char g_cvB[72 * 2 * B_T];                   // [tap*8+kb][ochalf]
__device__ __align__(128) char g_zeroA[AG_T];                         // never written -> zeros

__device__ __forceinline__ float gelu_exact(float v) {
    return 0.5f * v * (1.0f + erff(v * 0.70710678118654752f));
}
__device__ __forceinline__ uint32_t smem_to_u32(const void* p) {
    uint32_t a;
    asm("{ .reg .u64 t; cvta.to.shared.u64 t, %1; cvt.u32.u64 %0, t; }" : "=r"(a) : "l"(p));
    return a;
}

// ---- bulk copy + mbarrier ----
__device__ __forceinline__ void bulk_g2s(uint32_t dst, const void* src,
                                         uint32_t bytes, uint32_t mbar) {
    asm volatile(
        "cp.async.bulk.shared::cluster.global.mbarrier::complete_tx::bytes "
        "[%0], [%1], %2, [%3];"
        :: "r"(dst), "l"(src), "r"(bytes), "r"(mbar) : "memory");
}
#define MBARRIER_INIT(mbar, count) \
    asm volatile("mbarrier.init.shared.b64 [%0], %1;" :: "r"((uint32_t)(mbar)), "r"((uint32_t)(count)) : "memory")
#define MBARRIER_EXPECT_TX(mbar, bytes) \
    asm volatile("mbarrier.arrive.expect_tx.shared.b64 _, [%0], %1;" :: "r"((uint32_t)(mbar)), "r"((uint32_t)(bytes)) : "memory")
#define MBARRIER_WAIT_PARITY(mbar_smem_addr, phase_parity) do { \
    uint32_t _mbar = (uint32_t)(mbar_smem_addr); \
    uint32_t _parity = (uint32_t)(phase_parity); \
    uint32_t _done; \
    asm volatile("{\n\t.reg .pred p;\n\t" \
        "mbarrier.try_wait.parity.acquire.cta.shared::cta.b64 p, [%1], %2;\n\t" \
        "selp.b32 %0, 1, 0, p;\n\t}" : "=r"(_done) : "r"(_mbar), "r"(_parity) : "memory"); \
    if (!_done) { \
        asm volatile("{\n\t.reg .pred P1;\n\t" \
            "WAIT_LOOP_%=:\n\t" \
            "mbarrier.try_wait.parity.acquire.cta.shared::cta.b64 P1, [%0], %1, 0x989680;\n\t" \
            "@P1 bra.uni WAIT_DONE_%=;\n\t" \
            "bra.uni WAIT_LOOP_%=;\n\t" \
            "WAIT_DONE_%=:\n\t}" :: "r"(_mbar), "r"(_parity) : "memory"); \
    } \
} while(0)

// ---- mma ----
__device__ __forceinline__ void ldsm4(uint32_t* r, uint32_t addr) {
    asm volatile("ldmatrix.sync.aligned.m8n8.x4.shared.b16 {%0,%1,%2,%3}, [%4];"
                 : "=r"(r[0]), "=r"(r[1]), "=r"(r[2]), "=r"(r[3]) : "r"(addr));
}
__device__ __forceinline__ void mma16816(float* c, const uint32_t* a,
                                         uint32_t b0, uint32_t b1) {
    asm volatile(
        "mma.sync.aligned.m16n8k16.row.col.f32.f16.f16.f32 "
        "{%0,%1,%2,%3}, {%4,%5,%6,%7}, {%8,%9}, {%0,%1,%2,%3};"
        : "+f"(c[0]), "+f"(c[1]), "+f"(c[2]), "+f"(c[3])
        : "r"(a[0]), "r"(a[1]), "r"(a[2]), "r"(a[3]), "r"(b0), "r"(b1));
}

// ---------------------------------------------------------------------------
// prep: dw weights, pw/cv weight tiles (fp16, smem-image, per oc-half)
// ---------------------------------------------------------------------------
__global__ void prep_kernel(const float* __restrict__ dw_w,
                            const float* __restrict__ pw_w,
                            const float* __restrict__ cv_w) {
    int idx0 = blockIdx.x * blockDim.x + threadIdx.x;
    int stride = gridDim.x * blockDim.x;
    for (int idx = idx0; idx < 9 * C4; idx += stride) {
        int tap = idx >> 8, c = idx & 255;
        g_dwT[idx] = dw_w[c * 9 + tap];
    }
    for (int idx = idx0; idx < C4 * C4; idx += stride) {
        int oc = idx >> 8, ic = idx & 255;
        size_t o = (size_t)((ic >> 5) * 2 + (oc >> 7)) * B_T
                 + (size_t)(oc & 127) * ROWP + (ic & 31) * 2;
        *(__half*)(g_pwB + o) = __float2half(pw_w[idx]);
    }
    for (int idx = idx0; idx < 9 * C4 * C4; idx += stride) {
        int tap = idx / (C4 * C4);
        int r = idx % (C4 * C4);
        int oc = r >> 8, ic = r & 255;
        float v = cv_w[((size_t)oc * C4 + ic) * 9 + tap];
        size_t o = (size_t)((tap * 8 + (ic >> 5)) * 2 + (oc >> 7)) * B_T
                 + (size_t)(oc & 127) * ROWP + (ic & 31) * 2;
        *(__half*)(g_cvB + o) = __float2half(v);
    }
}

// ---------------------------------------------------------------------------
// DWT + transpose:  x (NCHW) -> t0 (fp32 NHWC)
// ---------------------------------------------------------------------------
__global__ void dwt_kernel(const float* __restrict__ x) {
    __shared__ float4 s[16][17];
    int b = blockIdx.z, j = blockIdx.y;
    int ctile = blockIdx.x >> 3, itile = blockIdx.x & 7;
    int tx = threadIdx.x, ty = threadIdx.y;

    int c = ctile * 16 + ty, i = itile * 16 + tx;
    const float* p = x + (((size_t)(b * CC + c) * 256) + 2 * j) * 256 + 2 * i;
    float2 top = *(const float2*)p;
    float2 bot = *(const float2*)(p + 256);
    float a = top.x, bq = top.y, cq = bot.x, d = bot.y;
    s[ty][tx] = make_float4((a + bq + cq + d) * 0.5f, (a + bq - cq - d) * 0.5f,
                            (a - bq + cq - d) * 0.5f, (a - bq - cq + d) * 0.5f);
    __syncthreads();
    float4 v = s[tx][ty];
    int c2 = ctile * 16 + tx, i2 = itile * 16 + ty;
    *(float4*)(g_t0 + ((((size_t)b * H2 + i2) * W2) + j) * C4 + 4 * c2) = v;
}

// ---------------------------------------------------------------------------
// Depthwise 3x3 + bias, split to fp16 hi/lo, write packed pw-A tiles
// ---------------------------------------------------------------------------
__global__ void dw_kernel(const float* __restrict__ dw_b) {
    int cq = threadIdx.x;
    int j = blockIdx.x * 4 + threadIdx.y;
    int i = blockIdx.y, b = blockIdx.z;
    int c0 = cq * 4;

    float4 acc = *(const float4*)(dw_b + c0);
    #pragma unroll
    for (int tap = 0; tap < 9; ++tap) {
        int ii = i + tap / 3 - 1, jj = j + tap % 3 - 1;
        if ((unsigned)ii < (unsigned)H2 && (unsigned)jj < (unsigned)W2) {
            float4 v = *(const float4*)(g_t0 + ((((size_t)b * H2 + ii) * W2) + jj) * C4 + c0);
            float4 w = *(const float4*)(g_dwT + tap * C4 + c0);
            acc.x += v.x * w.x; acc.y += v.y * w.y;
            acc.z += v.z * w.z; acc.w += v.w * w.w;
        }
    }
    float vv[4] = {acc.x, acc.y, acc.z, acc.w};
    __half hb[4], lb[4];
    #pragma unroll
    for (int q = 0; q < 4; q++) {
        hb[q] = __float2half(vv[q]);
        lb[q] = __float2half(vv[q] - __half2float(hb[q]));
    }
    size_t o = (size_t)(((b * H2 + i) * 8) + (c0 >> 5)) * A_T
             + (size_t)j * ROWP + (c0 & 31) * 2;
    *(uint2*)(g_pwA_hi + o) = *(uint2*)hb;
    *(uint2*)(g_pwA_lo + o) = *(uint2*)lb;
}

// ---------------------------------------------------------------------------
// Unified fp16 2-pass HMMA GEMM: acc = (Ah + Al) * B.
// CTA: M=128(j) x N=128(oc-half), 256 thr, 4(m)x2(n) warps,
// 3-stage bulk ring, 2 CTAs/SM, single sync per chunk.
// IS_CV=false: pw (NC=8), out -> packed cv-A tiles (hi/lo, row j+1).
// IS_CV=true:  cv (NC=72), out -> g_t0 fp32 with bias+GELU.
// ---------------------------------------------------------------------------
template<bool IS_CV>
__device__ __forceinline__ void issue_chunk(uint32_t sb, uint32_t mb,
                                            int bi, int i, int oh, int c) {
    int s = c % NSTAGE;
    uint32_t st = sb + s * STAGE_B;
    const char *ah, *al, *bh;
    if (IS_CV) {
        int tap = c >> 3, kb = c & 7;
        int di = tap / 3 - 1, dj = tap % 3 - 1;
        int ii = i + di;
        if ((unsigned)ii < (unsigned)H2) {
            size_t blk = (size_t)(((bi & ~127) + ii) * 8 + kb) * AG_T + (size_t)(1 + dj) * ROWP;
            ah = g_cvA_hi + blk; al = g_cvA_lo + blk;
        } else {
            ah = g_zeroA; al = g_zeroA;
        }
        bh = g_cvB + (size_t)(c * 2 + oh) * B_T;
    } else {
        size_t blk = (size_t)(bi * 8 + c) * A_T;
        ah = g_pwA_hi + blk; al = g_pwA_lo + blk;
        bh = g_pwB + (size_t)(c * 2 + oh) * B_T;
    }
    uint32_t mbar = mb + s * 8;
    MBARRIER_EXPECT_TX(mbar, STAGE_B);
    bulk_g2s(st + OFF_AH, ah, A_T, mbar);
    bulk_g2s(st + OFF_AL, al, A_T, mbar);
    bulk_g2s(st + OFF_B,  bh, B_T, mbar);
}

template<int NC, bool IS_CV>
__global__ void __launch_bounds__(256, 2)
gemm_bulk_kernel(const float* __restrict__ bias) {
    extern __shared__ char smem[];
    uint32_t sb = smem_to_u32(smem);
    uint32_t mb = sb + NSTAGE * STAGE_B;
    const int t = threadIdx.x, lane = t & 31, wid = t >> 5;
    const int mw = wid & 3, nw = wid >> 2;     // 4(m) x 2(n), warp tile 32x64
    const int bi = blockIdx.x;
    const int oh = blockIdx.y;                 // oc half
    const int b = bi >> 7, i = bi & 127;

    if (t == 0) {
        #pragma unroll
        for (int s = 0; s < NSTAGE; s++) MBARRIER_INIT(mb + s * 8, 1);
    }
    __syncthreads();
    if (t == 0) {
        issue_chunk<IS_CV>(sb, mb, bi, i, oh, 0);
        issue_chunk<IS_CV>(sb, mb, bi, i, oh, 1);
    }

    float acc[2][8][4];
    #pragma unroll
    for (int tm = 0; tm < 2; tm++)
        #pragma unroll
        for (int tn = 0; tn < 8; tn++)
            #pragma unroll
            for (int q = 0; q < 4; q++) acc[tm][tn][q] = 0.0f;

    uint32_t aoff[2], boff[4];
    #pragma unroll
    for (int tm = 0; tm < 2; tm++)
        aoff[tm] = (mw * 32 + tm * 16 + (lane & 15)) * ROWP + (lane >> 4) * 16;
    #pragma unroll
    for (int g = 0; g < 4; g++)
        boff[g] = (nw * 64 + g * 16 + ((lane >> 4) & 1) * 8 + (lane & 7)) * ROWP
                + ((lane >> 3) & 1) * 16;

    int parity = 0;
    for (int c = 0; c < NC; c++) {
        int s = c % NSTAGE;
        MBARRIER_WAIT_PARITY(mb + s * 8, parity);
        if (s == NSTAGE - 1) parity ^= 1;
        __syncthreads();
        // stage (c+2)%3 was consumed at chunk c-1; all threads are past it.
        if (t == 0 && c + 2 < NC) issue_chunk<IS_CV>(sb, mb, bi, i, oh, c + 2);

        uint32_t st = sb + s * STAGE_B;
        uint32_t Ahp = st + OFF_AH, Alp = st + OFF_AL, Bp = st + OFF_B;

        #pragma unroll
        for (int kh = 0; kh < 2; kh++) {
            uint32_t a_hi[2][4], a_lo[2][4], bf[4][4];
            #pragma unroll
            for (int tm = 0; tm < 2; tm++) ldsm4(a_hi[tm], Ahp + aoff[tm] + kh * 32);
            #pragma unroll
            for (int g = 0; g < 4; g++) ldsm4(bf[g], Bp + boff[g] + kh * 32);
            #pragma unroll
            for (int tm = 0; tm < 2; tm++)
                #pragma unroll
                for (int g = 0; g < 4; g++) {
                    mma16816(acc[tm][2 * g],     a_hi[tm], bf[g][0], bf[g][1]);
                    mma16816(acc[tm][2 * g + 1], a_hi[tm], bf[g][2], bf[g][3]);
                }
            #pragma unroll
            for (int tm = 0; tm < 2; tm++) ldsm4(a_lo[tm], Alp + aoff[tm] + kh * 32);
            #pragma unroll
            for (int tm = 0; tm < 2; tm++)
                #pragma unroll
                for (int g = 0; g < 4; g++) {
                    mma16816(acc[tm][2 * g],     a_lo[tm], bf[g][0], bf[g][1]);
                    mma16816(acc[tm][2 * g + 1], a_lo[tm], bf[g][2], bf[g][3]);
                }
        }
    }

    // Epilogue
    const int r = lane >> 2, cp = (lane & 3) * 2;
    #pragma unroll
    for (int tm = 0; tm < 2; tm++) {
        #pragma unroll
        for (int tn = 0; tn < 8; tn++) {
            int oc = oh * 128 + nw * 64 + tn * 8 + cp;
            float bz0 = __ldg(bias + oc), bz1 = __ldg(bias + oc + 1);
            int j0 = mw * 32 + tm * 16 + r;
            #pragma unroll
            for (int half = 0; half < 2; half++) {
                int j = j0 + half * 8;
                float v0 = acc[tm][tn][half * 2 + 0] + bz0;
                float v1 = acc[tm][tn][half * 2 + 1] + bz1;
                if (IS_CV) {
                    size_t off = ((((size_t)b * H2 + i) * W2) + j) * C4 + oc;
                    *(float2*)(g_t0 + off) = make_float2(gelu_exact(v0), gelu_exact(v1));
                } else {
                    __half h0 = __float2half(v0);
                    __half h1 = __float2half(v1);
                    __half l0 = __float2half(v0 - __half2float(h0));
                    __half l1 = __float2half(v1 - __half2float(h1));
                    __half hp[2] = {h0, h1};
                    __half lp[2] = {l0, l1};
                    size_t o = (size_t)((bi * 8) + (oc >> 5)) * AG_T
                             + (size_t)(j + 1) * ROWP + (oc & 31) * 2;
                    *(uint32_t*)(g_cvA_hi + o) = *(uint32_t*)hp;
                    *(uint32_t*)(g_cvA_lo + o) = *(uint32_t*)lp;
                }
            }
        }
    }
}

// ---------------------------------------------------------------------------
// IDWT: t0 (fp32 NHWC) -> out (NCHW)
// ---------------------------------------------------------------------------
__global__ void idwt_kernel(float* __restrict__ out) {
    __shared__ float4 s[16][17];
    int b = blockIdx.z, h2 = blockIdx.y;
    int ctile = blockIdx.x >> 3, wtile = blockIdx.x & 7;
    int tx = threadIdx.x, ty = threadIdx.y;

    int c = ctile * 16 + tx, w2 = wtile * 16 + ty;
    s[ty][tx] = *(const float4*)(g_t0 + ((((size_t)b * H2 + w2) * W2) + h2) * C4 + 4 * c);
    __syncthreads();

    float4 v = s[tx][ty];
    int c2 = ctile * 16 + ty, w2b = wtile * 16 + tx;
    float ll = v.x, ch = v.y, cv = v.z, cd = v.w;
    float a  = (ll + ch + cv + cd) * 0.5f;
    float bq = (ll + ch - cv - cd) * 0.5f;
    float cq = (ll - ch + cv - cd) * 0.5f;
    float dq = (ll - ch - cv + cd) * 0.5f;
    float* o = out + (((size_t)(b * CC + c2) * 256) + 2 * h2) * 256 + 2 * w2b;
    *(float2*)o         = make_float2(a, bq);
    *(float2*)(o + 256) = make_float2(cq, dq);
}

// ---------------------------------------------------------------------------
extern "C" void kernel_launch(void* const* d_in, const int* in_sizes, int n_in,
                              void* d_out, int out_size) {
    const float* x    = (const float*)d_in[0];
    const float* dw_w = (const float*)d_in[1];
    const float* dw_b = (const float*)d_in[2];
    const float* pw_w = (const float*)d_in[3];
    const float* pw_b = (const float*)d_in[4];
    const float* cv_w = (const float*)d_in[5];
    const float* cv_b = (const float*)d_in[6];
    float* out = (float*)d_out;

    cudaFuncSetAttribute(gemm_bulk_kernel<8, false>,
                         cudaFuncAttributeMaxDynamicSharedMemorySize, SMEM_DYN);
    cudaFuncSetAttribute(gemm_bulk_kernel<72, true>,
                         cudaFuncAttributeMaxDynamicSharedMemorySize, SMEM_DYN);

    prep_kernel<<<1024, 256>>>(dw_w, pw_w, cv_w);
    dwt_kernel<<<dim3(32, 128, BB), dim3(16, 16)>>>(x);
    dw_kernel<<<dim3(32, 128, BB), dim3(64, 4)>>>(dw_b);
    gemm_bulk_kernel<8, false><<<dim3(1024, 2), 256, SMEM_DYN>>>(pw_b);
    gemm_bulk_kernel<72, true><<<dim3(1024, 2), 256, SMEM_DYN>>>(cv_b);
    idwt_kernel<<<dim3(32, 128, BB), dim3(16, 16)>>>(out);
}

// round 10
// speedup vs baseline: 5.6857x; 1.5326x over previous
#include <cuda_runtime.h>
#include <cuda_fp16.h>
#include <math.h>
#include <stdint.h>

#define BB 8
#define CC 64
#define C4 256
#define H2 128
#define W2 128

// ---------------------------------------------------------------------------
// Tile geometry: byte-exact smem images, 80B-padded rows
// ---------------------------------------------------------------------------
#define ROWP 80
#define A_T (128 * ROWP)            // 10240  A tile (128 j-rows)
#define AG_T (130 * ROWP)           // 10400  guarded A block (halo rows 0,129)
#define B_T (128 * ROWP)            // 10240  B tile (128 oc rows = one half)

// ---------------------------------------------------------------------------
// Global scratch
// ---------------------------------------------------------------------------
__device__ float g_t0[(size_t)BB * H2 * W2 * C4];      // dwt out / cv out (fp32 NHWC)
__device__ float g_dwT[9 * C4];

// packed tiles (smem images), fp16; A-side single, pw-W split hi/lo
__device__ __align__(128) char g_pwA[(size_t)BB * H2 * 8 * A_T];      // [b*128+i][chunk]
__device__ __align__(128) char g_pwBh[8 * 2 * B_T];                   // [chunk][ochalf]
__device__ __align__(128) char g_pwBl[8 * 2 * B_T];
__device__ __align__(128) char g_cvA[(size_t)BB * H2 * 8 * AG_T];     // [b*128+i][kb] guarded
__device__ __align__(128) char g_cvB[72 * 2 * B_T];                   // [tap*8+kb][ochalf]
__device__ __align__(128) char g_zeroA[AG_T];                         // never written -> zeros

__device__ __forceinline__ float gelu_exact(float v) {
    return 0.5f * v * (1.0f + erff(v * 0.70710678118654752f));
}
__device__ __forceinline__ uint32_t smem_to_u32(const void* p) {
    uint32_t a;
    asm("{ .reg .u64 t; cvta.to.shared.u64 t, %1; cvt.u32.u64 %0, t; }" : "=r"(a) : "l"(p));
    return a;
}

// ---- bulk copy + mbarrier ----
__device__ __forceinline__ void bulk_g2s(uint32_t dst, const void* src,
                                         uint32_t bytes, uint32_t mbar) {
    asm volatile(
        "cp.async.bulk.shared::cluster.global.mbarrier::complete_tx::bytes "
        "[%0], [%1], %2, [%3];"
        :: "r"(dst), "l"(src), "r"(bytes), "r"(mbar) : "memory");
}
#define MBARRIER_INIT(mbar, count) \
    asm volatile("mbarrier.init.shared.b64 [%0], %1;" :: "r"((uint32_t)(mbar)), "r"((uint32_t)(count)) : "memory")
#define MBARRIER_EXPECT_TX(mbar, bytes) \
    asm volatile("mbarrier.arrive.expect_tx.shared.b64 _, [%0], %1;" :: "r"((uint32_t)(mbar)), "r"((uint32_t)(bytes)) : "memory")
#define MBARRIER_WAIT_PARITY(mbar_smem_addr, phase_parity) do { \
    uint32_t _mbar = (uint32_t)(mbar_smem_addr); \
    uint32_t _parity = (uint32_t)(phase_parity); \
    uint32_t _done; \
    asm volatile("{\n\t.reg .pred p;\n\t" \
        "mbarrier.try_wait.parity.acquire.cta.shared::cta.b64 p, [%1], %2;\n\t" \
        "selp.b32 %0, 1, 0, p;\n\t}" : "=r"(_done) : "r"(_mbar), "r"(_parity) : "memory"); \
    if (!_done) { \
        asm volatile("{\n\t.reg .pred P1;\n\t" \
            "WAIT_LOOP_%=:\n\t" \
            "mbarrier.try_wait.parity.acquire.cta.shared::cta.b64 P1, [%0], %1, 0x989680;\n\t" \
            "@P1 bra.uni WAIT_DONE_%=;\n\t" \
            "bra.uni WAIT_LOOP_%=;\n\t" \
            "WAIT_DONE_%=:\n\t}" :: "r"(_mbar), "r"(_parity) : "memory"); \
    } \
} while(0)

// ---- mma ----
__device__ __forceinline__ void ldsm4(uint32_t* r, uint32_t addr) {
    asm volatile("ldmatrix.sync.aligned.m8n8.x4.shared.b16 {%0,%1,%2,%3}, [%4];"
                 : "=r"(r[0]), "=r"(r[1]), "=r"(r[2]), "=r"(r[3]) : "r"(addr));
}
__device__ __forceinline__ void mma16816(float* c, const uint32_t* a,
                                         uint32_t b0, uint32_t b1) {
    asm volatile(
        "mma.sync.aligned.m16n8k16.row.col.f32.f16.f16.f32 "
        "{%0,%1,%2,%3}, {%4,%5,%6,%7}, {%8,%9}, {%0,%1,%2,%3};"
        : "+f"(c[0]), "+f"(c[1]), "+f"(c[2]), "+f"(c[3])
        : "r"(a[0]), "r"(a[1]), "r"(a[2]), "r"(a[3]), "r"(b0), "r"(b1));
}

// ---------------------------------------------------------------------------
// prep: dw weights, pw weight hi/lo tiles, cv weight tiles (fp16 smem images)
// ---------------------------------------------------------------------------
__global__ void prep_kernel(const float* __restrict__ dw_w,
                            const float* __restrict__ pw_w,
                            const float* __restrict__ cv_w) {
    int idx0 = blockIdx.x * blockDim.x + threadIdx.x;
    int stride = gridDim.x * blockDim.x;
    for (int idx = idx0; idx < 9 * C4; idx += stride) {
        int tap = idx >> 8, c = idx & 255;
        g_dwT[idx] = dw_w[c * 9 + tap];
    }
    for (int idx = idx0; idx < C4 * C4; idx += stride) {
        int oc = idx >> 8, ic = idx & 255;
        float v = pw_w[idx];
        __half h = __float2half(v);
        __half l = __float2half(v - __half2float(h));
        size_t o = (size_t)((ic >> 5) * 2 + (oc >> 7)) * B_T
                 + (size_t)(oc & 127) * ROWP + (ic & 31) * 2;
        *(__half*)(g_pwBh + o) = h;
        *(__half*)(g_pwBl + o) = l;
    }
    for (int idx = idx0; idx < 9 * C4 * C4; idx += stride) {
        int tap = idx / (C4 * C4);
        int r = idx % (C4 * C4);
        int oc = r >> 8, ic = r & 255;
        float v = cv_w[((size_t)oc * C4 + ic) * 9 + tap];
        size_t o = (size_t)((tap * 8 + (ic >> 5)) * 2 + (oc >> 7)) * B_T
                 + (size_t)(oc & 127) * ROWP + (ic & 31) * 2;
        *(__half*)(g_cvB + o) = __float2half(v);
    }
}

// ---------------------------------------------------------------------------
// DWT + transpose:  x (NCHW) -> t0 (fp32 NHWC)
// ---------------------------------------------------------------------------
__global__ void dwt_kernel(const float* __restrict__ x) {
    __shared__ float4 s[16][17];
    int b = blockIdx.z, j = blockIdx.y;
    int ctile = blockIdx.x >> 3, itile = blockIdx.x & 7;
    int tx = threadIdx.x, ty = threadIdx.y;

    int c = ctile * 16 + ty, i = itile * 16 + tx;
    const float* p = x + (((size_t)(b * CC + c) * 256) + 2 * j) * 256 + 2 * i;
    float2 top = *(const float2*)p;
    float2 bot = *(const float2*)(p + 256);
    float a = top.x, bq = top.y, cq = bot.x, d = bot.y;
    s[ty][tx] = make_float4((a + bq + cq + d) * 0.5f, (a + bq - cq - d) * 0.5f,
                            (a - bq + cq - d) * 0.5f, (a - bq - cq + d) * 0.5f);
    __syncthreads();
    float4 v = s[tx][ty];
    int c2 = ctile * 16 + tx, i2 = itile * 16 + ty;
    *(float4*)(g_t0 + ((((size_t)b * H2 + i2) * W2) + j) * C4 + 4 * c2) = v;
}

// ---------------------------------------------------------------------------
// Depthwise 3x3 + bias (fp32), write single-fp16 packed pw-A tiles
// ---------------------------------------------------------------------------
__global__ void dw_kernel(const float* __restrict__ dw_b) {
    int cq = threadIdx.x;
    int j = blockIdx.x * 4 + threadIdx.y;
    int i = blockIdx.y, b = blockIdx.z;
    int c0 = cq * 4;

    float4 acc = *(const float4*)(dw_b + c0);
    #pragma unroll
    for (int tap = 0; tap < 9; ++tap) {
        int ii = i + tap / 3 - 1, jj = j + tap % 3 - 1;
        if ((unsigned)ii < (unsigned)H2 && (unsigned)jj < (unsigned)W2) {
            float4 v = *(const float4*)(g_t0 + ((((size_t)b * H2 + ii) * W2) + jj) * C4 + c0);
            float4 w = *(const float4*)(g_dwT + tap * C4 + c0);
            acc.x += v.x * w.x; acc.y += v.y * w.y;
            acc.z += v.z * w.z; acc.w += v.w * w.w;
        }
    }
    __half hb[4] = {__float2half(acc.x), __float2half(acc.y),
                    __float2half(acc.z), __float2half(acc.w)};
    size_t o = (size_t)(((b * H2 + i) * 8) + (c0 >> 5)) * A_T
             + (size_t)j * ROWP + (c0 & 31) * 2;
    *(uint2*)(g_pwA + o) = *(uint2*)hb;
}

// ---------------------------------------------------------------------------
// Unified fp16 HMMA GEMM. CTA: M=128(j) x N=128(oc-half), 256 thr, 4x2 warps.
// Grid: (oh, bi) -- oh fastest for A-tile L2 reuse.
// IS_CV=false: pw, 2 passes A*Wh + A*Wl, 3-stage ring; out -> packed cv-A.
// IS_CV=true:  cv, 1 pass A*W, 4-stage ring; out -> g_t0 fp32 bias+GELU.
// ---------------------------------------------------------------------------
template<bool IS_CV>
__device__ __forceinline__ void issue_chunk(uint32_t sb, uint32_t mb,
                                            int bi, int i, int oh, int c) {
    constexpr int NST = IS_CV ? 4 : 3;
    constexpr uint32_t STG = IS_CV ? (A_T + B_T) : (A_T + 2 * B_T);
    int s = c % NST;
    uint32_t st = sb + s * STG;
    uint32_t mbar = mb + s * 8;
    MBARRIER_EXPECT_TX(mbar, STG);
    if (IS_CV) {
        int tap = c >> 3, kb = c & 7;
        int di = tap / 3 - 1, dj = tap % 3 - 1;
        int ii = i + di;
        const char* ap;
        if ((unsigned)ii < (unsigned)H2)
            ap = g_cvA + (size_t)(((bi & ~127) + ii) * 8 + kb) * AG_T + (size_t)(1 + dj) * ROWP;
        else
            ap = g_zeroA;
        bulk_g2s(st, ap, A_T, mbar);
        bulk_g2s(st + A_T, g_cvB + (size_t)(c * 2 + oh) * B_T, B_T, mbar);
    } else {
        bulk_g2s(st, g_pwA + (size_t)(bi * 8 + c) * A_T, A_T, mbar);
        bulk_g2s(st + A_T, g_pwBh + (size_t)(c * 2 + oh) * B_T, B_T, mbar);
        bulk_g2s(st + A_T + B_T, g_pwBl + (size_t)(c * 2 + oh) * B_T, B_T, mbar);
    }
}

template<int NC, bool IS_CV>
__global__ void __launch_bounds__(256, 2)
gemm_bulk_kernel(const float* __restrict__ bias) {
    constexpr int NST = IS_CV ? 4 : 3;
    constexpr uint32_t STG = IS_CV ? (A_T + B_T) : (A_T + 2 * B_T);
    extern __shared__ char smem[];
    uint32_t sb = smem_to_u32(smem);
    uint32_t mb = sb + NST * STG;
    const int t = threadIdx.x, lane = t & 31, wid = t >> 5;
    const int mw = wid & 3, nw = wid >> 2;     // 4(m) x 2(n), warp tile 32x64
    const int oh = blockIdx.x;                 // oc half (fastest -> L2 reuse)
    const int bi = blockIdx.y;
    const int b = bi >> 7, i = bi & 127;

    if (t == 0) {
        #pragma unroll
        for (int s = 0; s < NST; s++) MBARRIER_INIT(mb + s * 8, 1);
    }
    __syncthreads();
    if (t == 0) {
        #pragma unroll
        for (int c = 0; c < NST - 1; c++) issue_chunk<IS_CV>(sb, mb, bi, i, oh, c);
    }

    float acc[2][8][4];
    #pragma unroll
    for (int tm = 0; tm < 2; tm++)
        #pragma unroll
        for (int tn = 0; tn < 8; tn++)
            #pragma unroll
            for (int q = 0; q < 4; q++) acc[tm][tn][q] = 0.0f;

    uint32_t aoff[2], boff[4];
    #pragma unroll
    for (int tm = 0; tm < 2; tm++)
        aoff[tm] = (mw * 32 + tm * 16 + (lane & 15)) * ROWP + (lane >> 4) * 16;
    #pragma unroll
    for (int g = 0; g < 4; g++)
        boff[g] = (nw * 64 + g * 16 + ((lane >> 4) & 1) * 8 + (lane & 7)) * ROWP
                + ((lane >> 3) & 1) * 16;

    int parity = 0;
    for (int c = 0; c < NC; c++) {
        int s = c % NST;
        MBARRIER_WAIT_PARITY(mb + s * 8, parity);
        if (s == NST - 1) parity ^= 1;
        __syncthreads();
        // slot (c+NST-1)%NST was fully consumed at chunk c-1
        if (t == 0 && c + NST - 1 < NC) issue_chunk<IS_CV>(sb, mb, bi, i, oh, c + NST - 1);

        uint32_t st = sb + s * STG;

        #pragma unroll
        for (int kh = 0; kh < 2; kh++) {
            uint32_t a[2][4], bf[4][4];
            #pragma unroll
            for (int tm = 0; tm < 2; tm++) ldsm4(a[tm], st + aoff[tm] + kh * 32);
            #pragma unroll
            for (int g = 0; g < 4; g++) ldsm4(bf[g], st + A_T + boff[g] + kh * 32);
            #pragma unroll
            for (int tm = 0; tm < 2; tm++)
                #pragma unroll
                for (int g = 0; g < 4; g++) {
                    mma16816(acc[tm][2 * g],     a[tm], bf[g][0], bf[g][1]);
                    mma16816(acc[tm][2 * g + 1], a[tm], bf[g][2], bf[g][3]);
                }
            if (!IS_CV) {   // second pass: A * Wl
                #pragma unroll
                for (int g = 0; g < 4; g++) ldsm4(bf[g], st + A_T + B_T + boff[g] + kh * 32);
                #pragma unroll
                for (int tm = 0; tm < 2; tm++)
                    #pragma unroll
                    for (int g = 0; g < 4; g++) {
                        mma16816(acc[tm][2 * g],     a[tm], bf[g][0], bf[g][1]);
                        mma16816(acc[tm][2 * g + 1], a[tm], bf[g][2], bf[g][3]);
                    }
            }
        }
    }

    // Epilogue
    const int r = lane >> 2, cp = (lane & 3) * 2;
    #pragma unroll
    for (int tm = 0; tm < 2; tm++) {
        #pragma unroll
        for (int tn = 0; tn < 8; tn++) {
            int oc = oh * 128 + nw * 64 + tn * 8 + cp;
            float bz0 = __ldg(bias + oc), bz1 = __ldg(bias + oc + 1);
            int j0 = mw * 32 + tm * 16 + r;
            #pragma unroll
            for (int half = 0; half < 2; half++) {
                int j = j0 + half * 8;
                float v0 = acc[tm][tn][half * 2 + 0] + bz0;
                float v1 = acc[tm][tn][half * 2 + 1] + bz1;
                if (IS_CV) {
                    size_t off = ((((size_t)b * H2 + i) * W2) + j) * C4 + oc;
                    *(float2*)(g_t0 + off) = make_float2(gelu_exact(v0), gelu_exact(v1));
                } else {
                    __half hp[2] = {__float2half(v0), __float2half(v1)};
                    size_t o = (size_t)((bi * 8) + (oc >> 5)) * AG_T
                             + (size_t)(j + 1) * ROWP + (oc & 31) * 2;
                    *(uint32_t*)(g_cvA + o) = *(uint32_t*)hp;
                }
            }
        }
    }
}

// ---------------------------------------------------------------------------
// IDWT: t0 (fp32 NHWC) -> out (NCHW)
// ---------------------------------------------------------------------------
__global__ void idwt_kernel(float* __restrict__ out) {
    __shared__ float4 s[16][17];
    int b = blockIdx.z, h2 = blockIdx.y;
    int ctile = blockIdx.x >> 3, wtile = blockIdx.x & 7;
    int tx = threadIdx.x, ty = threadIdx.y;

    int c = ctile * 16 + tx, w2 = wtile * 16 + ty;
    s[ty][tx] = *(const float4*)(g_t0 + ((((size_t)b * H2 + w2) * W2) + h2) * C4 + 4 * c);
    __syncthreads();

    float4 v = s[tx][ty];
    int c2 = ctile * 16 + ty, w2b = wtile * 16 + tx;
    float ll = v.x, ch = v.y, cv = v.z, cd = v.w;
    float a  = (ll + ch + cv + cd) * 0.5f;
    float bq = (ll + ch - cv - cd) * 0.5f;
    float cq = (ll - ch + cv - cd) * 0.5f;
    float dq = (ll - ch - cv + cd) * 0.5f;
    float* o = out + (((size_t)(b * CC + c2) * 256) + 2 * h2) * 256 + 2 * w2b;
    *(float2*)o         = make_float2(a, bq);
    *(float2*)(o + 256) = make_float2(cq, dq);
}

// ---------------------------------------------------------------------------
extern "C" void kernel_launch(void* const* d_in, const int* in_sizes, int n_in,
                              void* d_out, int out_size) {
    const float* x    = (const float*)d_in[0];
    const float* dw_w = (const float*)d_in[1];
    const float* dw_b = (const float*)d_in[2];
    const float* pw_w = (const float*)d_in[3];
    const float* pw_b = (const float*)d_in[4];
    const float* cv_w = (const float*)d_in[5];
    const float* cv_b = (const float*)d_in[6];
    float* out = (float*)d_out;

    constexpr int SMEM_PW = 3 * (A_T + 2 * B_T) + 64;   // 92224
    constexpr int SMEM_CV = 4 * (A_T + B_T) + 64;       // 81984

    cudaFuncSetAttribute(gemm_bulk_kernel<8, false>,
                         cudaFuncAttributeMaxDynamicSharedMemorySize, SMEM_PW);
    cudaFuncSetAttribute(gemm_bulk_kernel<72, true>,
                         cudaFuncAttributeMaxDynamicSharedMemorySize, SMEM_CV);

    prep_kernel<<<1024, 256>>>(dw_w, pw_w, cv_w);
    dwt_kernel<<<dim3(32, 128, BB), dim3(16, 16)>>>(x);
    dw_kernel<<<dim3(32, 128, BB), dim3(64, 4)>>>(dw_b);
    gemm_bulk_kernel<8, false><<<dim3(2, 1024), 256, SMEM_PW>>>(pw_b);
    gemm_bulk_kernel<72, true><<<dim3(2, 1024), 256, SMEM_CV>>>(cv_b);
    idwt_kernel<<<dim3(32, 128, BB), dim3(16, 16)>>>(out);
}

// round 11
// speedup vs baseline: 5.9190x; 1.0410x over previous
#include <cuda_runtime.h>
#include <cuda_fp16.h>
#include <math.h>
#include <stdint.h>

#define BB 8
#define CC 64
#define C4 256
#define H2 128
#define W2 128

// ---------------------------------------------------------------------------
// Tile geometry: byte-exact smem images, 80B-padded rows
// ---------------------------------------------------------------------------
#define ROWP 80
#define A_T (128 * ROWP)            // 10240  A tile (128 j-rows)
#define AG_T (130 * ROWP)           // 10400  guarded A block (halo rows 0,129)
#define B_T (128 * ROWP)            // 10240  B tile (128 oc rows = one half)

// pw: 4-stage ring, single-pass chunks
#define PW_STG (A_T + B_T)          // 20480
#define PW_NST 4
#define SMEM_PW (PW_NST * PW_STG + 64)      // 81984 -> 2 CTAs/SM

// cv: 2-stage ring of super-chunks (guarded A block + 3 B tiles)
#define CV_STG (AG_T + 3 * B_T)     // 41120
#define CV_NST 2
#define SMEM_CV (CV_NST * CV_STG + 64)      // 82304 -> 2 CTAs/SM

// ---------------------------------------------------------------------------
// Global scratch
// ---------------------------------------------------------------------------
__device__ float g_t0[(size_t)BB * H2 * W2 * C4];      // dwt out / cv out (fp32 NHWC)
__device__ float g_dwT[9 * C4];

// packed tiles (smem images), all single fp16
__device__ __align__(128) char g_pwA[(size_t)BB * H2 * 8 * A_T];      // [b*128+i][chunk]
__device__ __align__(128) char g_pwB[8 * 2 * B_T];                    // [chunk][ochalf]
__device__ __align__(128) char g_cvA[(size_t)BB * H2 * 8 * AG_T];     // [b*128+i][kb] guarded
__device__ __align__(128) char g_cvB[72 * 2 * B_T];                   // [tap*8+kb][ochalf]
__device__ __align__(128) char g_zeroA[AG_T];                         // never written -> zeros

__device__ __forceinline__ float gelu_exact(float v) {
    return 0.5f * v * (1.0f + erff(v * 0.70710678118654752f));
}
__device__ __forceinline__ uint32_t smem_to_u32(const void* p) {
    uint32_t a;
    asm("{ .reg .u64 t; cvta.to.shared.u64 t, %1; cvt.u32.u64 %0, t; }" : "=r"(a) : "l"(p));
    return a;
}

// ---- bulk copy + mbarrier ----
__device__ __forceinline__ void bulk_g2s(uint32_t dst, const void* src,
                                         uint32_t bytes, uint32_t mbar) {
    asm volatile(
        "cp.async.bulk.shared::cluster.global.mbarrier::complete_tx::bytes "
        "[%0], [%1], %2, [%3];"
        :: "r"(dst), "l"(src), "r"(bytes), "r"(mbar) : "memory");
}
#define MBARRIER_INIT(mbar, count) \
    asm volatile("mbarrier.init.shared.b64 [%0], %1;" :: "r"((uint32_t)(mbar)), "r"((uint32_t)(count)) : "memory")
#define MBARRIER_EXPECT_TX(mbar, bytes) \
    asm volatile("mbarrier.arrive.expect_tx.shared.b64 _, [%0], %1;" :: "r"((uint32_t)(mbar)), "r"((uint32_t)(bytes)) : "memory")
#define MBARRIER_WAIT_PARITY(mbar_smem_addr, phase_parity) do { \
    uint32_t _mbar = (uint32_t)(mbar_smem_addr); \
    uint32_t _parity = (uint32_t)(phase_parity); \
    uint32_t _done; \
    asm volatile("{\n\t.reg .pred p;\n\t" \
        "mbarrier.try_wait.parity.acquire.cta.shared::cta.b64 p, [%1], %2;\n\t" \
        "selp.b32 %0, 1, 0, p;\n\t}" : "=r"(_done) : "r"(_mbar), "r"(_parity) : "memory"); \
    if (!_done) { \
        asm volatile("{\n\t.reg .pred P1;\n\t" \
            "WAIT_LOOP_%=:\n\t" \
            "mbarrier.try_wait.parity.acquire.cta.shared::cta.b64 P1, [%0], %1, 0x989680;\n\t" \
            "@P1 bra.uni WAIT_DONE_%=;\n\t" \
            "bra.uni WAIT_LOOP_%=;\n\t" \
            "WAIT_DONE_%=:\n\t}" :: "r"(_mbar), "r"(_parity) : "memory"); \
    } \
} while(0)

// ---- mma ----
__device__ __forceinline__ void ldsm4(uint32_t* r, uint32_t addr) {
    asm volatile("ldmatrix.sync.aligned.m8n8.x4.shared.b16 {%0,%1,%2,%3}, [%4];"
                 : "=r"(r[0]), "=r"(r[1]), "=r"(r[2]), "=r"(r[3]) : "r"(addr));
}
__device__ __forceinline__ void mma16816(float* c, const uint32_t* a,
                                         uint32_t b0, uint32_t b1) {
    asm volatile(
        "mma.sync.aligned.m16n8k16.row.col.f32.f16.f16.f32 "
        "{%0,%1,%2,%3}, {%4,%5,%6,%7}, {%8,%9}, {%0,%1,%2,%3};"
        : "+f"(c[0]), "+f"(c[1]), "+f"(c[2]), "+f"(c[3])
        : "r"(a[0]), "r"(a[1]), "r"(a[2]), "r"(a[3]), "r"(b0), "r"(b1));
}

// ---------------------------------------------------------------------------
// prep: dw weights, pw/cv weight tiles (single fp16 smem images)
// ---------------------------------------------------------------------------
__global__ void prep_kernel(const float* __restrict__ dw_w,
                            const float* __restrict__ pw_w,
                            const float* __restrict__ cv_w) {
    int idx0 = blockIdx.x * blockDim.x + threadIdx.x;
    int stride = gridDim.x * blockDim.x;
    for (int idx = idx0; idx < 9 * C4; idx += stride) {
        int tap = idx >> 8, c = idx & 255;
        g_dwT[idx] = dw_w[c * 9 + tap];
    }
    for (int idx = idx0; idx < C4 * C4; idx += stride) {
        int oc = idx >> 8, ic = idx & 255;
        size_t o = (size_t)((ic >> 5) * 2 + (oc >> 7)) * B_T
                 + (size_t)(oc & 127) * ROWP + (ic & 31) * 2;
        *(__half*)(g_pwB + o) = __float2half(pw_w[idx]);
    }
    for (int idx = idx0; idx < 9 * C4 * C4; idx += stride) {
        int tap = idx / (C4 * C4);
        int r = idx % (C4 * C4);
        int oc = r >> 8, ic = r & 255;
        float v = cv_w[((size_t)oc * C4 + ic) * 9 + tap];
        size_t o = (size_t)((tap * 8 + (ic >> 5)) * 2 + (oc >> 7)) * B_T
                 + (size_t)(oc & 127) * ROWP + (ic & 31) * 2;
        *(__half*)(g_cvB + o) = __float2half(v);
    }
}

// ---------------------------------------------------------------------------
// DWT + transpose:  x (NCHW) -> t0 (fp32 NHWC)
// ---------------------------------------------------------------------------
__global__ void dwt_kernel(const float* __restrict__ x) {
    __shared__ float4 s[16][17];
    int b = blockIdx.z, j = blockIdx.y;
    int ctile = blockIdx.x >> 3, itile = blockIdx.x & 7;
    int tx = threadIdx.x, ty = threadIdx.y;

    int c = ctile * 16 + ty, i = itile * 16 + tx;
    const float* p = x + (((size_t)(b * CC + c) * 256) + 2 * j) * 256 + 2 * i;
    float2 top = *(const float2*)p;
    float2 bot = *(const float2*)(p + 256);
    float a = top.x, bq = top.y, cq = bot.x, d = bot.y;
    s[ty][tx] = make_float4((a + bq + cq + d) * 0.5f, (a + bq - cq - d) * 0.5f,
                            (a - bq + cq - d) * 0.5f, (a - bq - cq + d) * 0.5f);
    __syncthreads();
    float4 v = s[tx][ty];
    int c2 = ctile * 16 + tx, i2 = itile * 16 + ty;
    *(float4*)(g_t0 + ((((size_t)b * H2 + i2) * W2) + j) * C4 + 4 * c2) = v;
}

// ---------------------------------------------------------------------------
// Depthwise 3x3 + bias (fp32), write single-fp16 packed pw-A tiles
// ---------------------------------------------------------------------------
__global__ void dw_kernel(const float* __restrict__ dw_b) {
    int cq = threadIdx.x;
    int j = blockIdx.x * 4 + threadIdx.y;
    int i = blockIdx.y, b = blockIdx.z;
    int c0 = cq * 4;

    float4 acc = *(const float4*)(dw_b + c0);
    #pragma unroll
    for (int tap = 0; tap < 9; ++tap) {
        int ii = i + tap / 3 - 1, jj = j + tap % 3 - 1;
        if ((unsigned)ii < (unsigned)H2 && (unsigned)jj < (unsigned)W2) {
            float4 v = *(const float4*)(g_t0 + ((((size_t)b * H2 + ii) * W2) + jj) * C4 + c0);
            float4 w = *(const float4*)(g_dwT + tap * C4 + c0);
            acc.x += v.x * w.x; acc.y += v.y * w.y;
            acc.z += v.z * w.z; acc.w += v.w * w.w;
        }
    }
    __half hb[4] = {__float2half(acc.x), __float2half(acc.y),
                    __float2half(acc.z), __float2half(acc.w)};
    size_t o = (size_t)(((b * H2 + i) * 8) + (c0 >> 5)) * A_T
             + (size_t)j * ROWP + (c0 & 31) * 2;
    *(uint2*)(g_pwA + o) = *(uint2*)hb;
}

// ---------------------------------------------------------------------------
// pw GEMM: single-pass fp16, CTA 128(j)x128(oc-half), 256 thr, 4x2 warps,
// 4-stage bulk ring (single sync/chunk), out -> packed cv-A fp16 tiles.
// ---------------------------------------------------------------------------
__device__ __forceinline__ void pw_issue(uint32_t sb, uint32_t mb,
                                         int bi, int oh, int c) {
    int s = c & 3;
    uint32_t st = sb + s * PW_STG;
    uint32_t mbar = mb + s * 8;
    MBARRIER_EXPECT_TX(mbar, PW_STG);
    bulk_g2s(st, g_pwA + (size_t)(bi * 8 + c) * A_T, A_T, mbar);
    bulk_g2s(st + A_T, g_pwB + (size_t)(c * 2 + oh) * B_T, B_T, mbar);
}

__global__ void __launch_bounds__(256, 2)
pw_gemm_kernel(const float* __restrict__ bias) {
    extern __shared__ char smem[];
    uint32_t sb = smem_to_u32(smem);
    uint32_t mb = sb + PW_NST * PW_STG;
    const int t = threadIdx.x, lane = t & 31, wid = t >> 5;
    const int mw = wid & 3, nw = wid >> 2;
    const int oh = blockIdx.x;
    const int bi = blockIdx.y;

    if (t == 0) {
        #pragma unroll
        for (int s = 0; s < PW_NST; s++) MBARRIER_INIT(mb + s * 8, 1);
    }
    __syncthreads();
    if (t == 0) {
        pw_issue(sb, mb, bi, oh, 0);
        pw_issue(sb, mb, bi, oh, 1);
        pw_issue(sb, mb, bi, oh, 2);
    }

    float acc[2][8][4];
    #pragma unroll
    for (int tm = 0; tm < 2; tm++)
        #pragma unroll
        for (int tn = 0; tn < 8; tn++)
            #pragma unroll
            for (int q = 0; q < 4; q++) acc[tm][tn][q] = 0.0f;

    uint32_t aoff[2], boff[4];
    #pragma unroll
    for (int tm = 0; tm < 2; tm++)
        aoff[tm] = (mw * 32 + tm * 16 + (lane & 15)) * ROWP + (lane >> 4) * 16;
    #pragma unroll
    for (int g = 0; g < 4; g++)
        boff[g] = (nw * 64 + g * 16 + ((lane >> 4) & 1) * 8 + (lane & 7)) * ROWP
                + ((lane >> 3) & 1) * 16;

    int parity = 0;
    for (int c = 0; c < 8; c++) {
        int s = c & 3;
        MBARRIER_WAIT_PARITY(mb + s * 8, parity);
        if (s == 3) parity ^= 1;
        __syncthreads();
        if (t == 0 && c + 3 < 8) pw_issue(sb, mb, bi, oh, c + 3);

        uint32_t st = sb + s * PW_STG;
        #pragma unroll
        for (int kh = 0; kh < 2; kh++) {
            uint32_t a[2][4], bf[4][4];
            #pragma unroll
            for (int tm = 0; tm < 2; tm++) ldsm4(a[tm], st + aoff[tm] + kh * 32);
            #pragma unroll
            for (int g = 0; g < 4; g++) ldsm4(bf[g], st + A_T + boff[g] + kh * 32);
            #pragma unroll
            for (int tm = 0; tm < 2; tm++)
                #pragma unroll
                for (int g = 0; g < 4; g++) {
                    mma16816(acc[tm][2 * g],     a[tm], bf[g][0], bf[g][1]);
                    mma16816(acc[tm][2 * g + 1], a[tm], bf[g][2], bf[g][3]);
                }
        }
    }

    const int r = lane >> 2, cp = (lane & 3) * 2;
    #pragma unroll
    for (int tm = 0; tm < 2; tm++) {
        #pragma unroll
        for (int tn = 0; tn < 8; tn++) {
            int oc = oh * 128 + nw * 64 + tn * 8 + cp;
            float bz0 = __ldg(bias + oc), bz1 = __ldg(bias + oc + 1);
            int j0 = mw * 32 + tm * 16 + r;
            #pragma unroll
            for (int half = 0; half < 2; half++) {
                int j = j0 + half * 8;
                float v0 = acc[tm][tn][half * 2 + 0] + bz0;
                float v1 = acc[tm][tn][half * 2 + 1] + bz1;
                __half hp[2] = {__float2half(v0), __float2half(v1)};
                size_t o = (size_t)((bi * 8) + (oc >> 5)) * AG_T
                         + (size_t)(j + 1) * ROWP + (oc & 31) * 2;
                *(uint32_t*)(g_cvA + o) = *(uint32_t*)hp;
            }
        }
    }
}

// ---------------------------------------------------------------------------
// cv GEMM: single-pass fp16 super-chunks. One guarded A block (130 rows)
// serves 3 taps (dj = -1,0,+1 via +80B smem base shifts). 24 super-chunks
// (di,kb), 2-stage ring, double sync. Out -> g_t0 fp32 bias+GELU.
// ---------------------------------------------------------------------------
__device__ __forceinline__ void cv_issue(uint32_t sb, uint32_t mb,
                                         int bi, int i, int oh, int sc) {
    int s = sc & 1;
    int di = sc >> 3, kb = sc & 7;
    int ii = i + di - 1;
    uint32_t st = sb + s * CV_STG;
    uint32_t mbar = mb + s * 8;
    MBARRIER_EXPECT_TX(mbar, CV_STG);
    const char* ap = ((unsigned)ii < (unsigned)H2)
        ? g_cvA + (size_t)(((bi & ~127) + ii) * 8 + kb) * AG_T
        : g_zeroA;
    bulk_g2s(st, ap, AG_T, mbar);
    #pragma unroll
    for (int djq = 0; djq < 3; djq++) {
        int tap = di * 3 + djq;
        bulk_g2s(st + AG_T + djq * B_T,
                 g_cvB + (size_t)((tap * 8 + kb) * 2 + oh) * B_T, B_T, mbar);
    }
}

__global__ void __launch_bounds__(256, 2)
cv_gemm_kernel(const float* __restrict__ bias) {
    extern __shared__ char smem[];
    uint32_t sb = smem_to_u32(smem);
    uint32_t mb = sb + CV_NST * CV_STG;
    const int t = threadIdx.x, lane = t & 31, wid = t >> 5;
    const int mw = wid & 3, nw = wid >> 2;
    const int oh = blockIdx.x;
    const int bi = blockIdx.y;
    const int b = bi >> 7, i = bi & 127;

    if (t == 0) {
        MBARRIER_INIT(mb, 1);
        MBARRIER_INIT(mb + 8, 1);
    }
    __syncthreads();
    if (t == 0) {
        cv_issue(sb, mb, bi, i, oh, 0);
        cv_issue(sb, mb, bi, i, oh, 1);
    }

    float acc[2][8][4];
    #pragma unroll
    for (int tm = 0; tm < 2; tm++)
        #pragma unroll
        for (int tn = 0; tn < 8; tn++)
            #pragma unroll
            for (int q = 0; q < 4; q++) acc[tm][tn][q] = 0.0f;

    uint32_t aoff[2], boff[4];
    #pragma unroll
    for (int tm = 0; tm < 2; tm++)
        aoff[tm] = (mw * 32 + tm * 16 + (lane & 15)) * ROWP + (lane >> 4) * 16;
    #pragma unroll
    for (int g = 0; g < 4; g++)
        boff[g] = (nw * 64 + g * 16 + ((lane >> 4) & 1) * 8 + (lane & 7)) * ROWP
                + ((lane >> 3) & 1) * 16;

    for (int sc = 0; sc < 24; sc++) {
        int s = sc & 1;
        MBARRIER_WAIT_PARITY(mb + s * 8, (sc >> 1) & 1);
        __syncthreads();

        uint32_t st = sb + s * CV_STG;
        #pragma unroll
        for (int djq = 0; djq < 3; djq++) {
            uint32_t Ab = st + djq * ROWP;          // dj = djq-1 -> base (1+dj)*80
            uint32_t Bb = st + AG_T + djq * B_T;
            #pragma unroll
            for (int kh = 0; kh < 2; kh++) {
                uint32_t a[2][4], bf[4][4];
                #pragma unroll
                for (int tm = 0; tm < 2; tm++) ldsm4(a[tm], Ab + aoff[tm] + kh * 32);
                #pragma unroll
                for (int g = 0; g < 4; g++) ldsm4(bf[g], Bb + boff[g] + kh * 32);
                #pragma unroll
                for (int tm = 0; tm < 2; tm++)
                    #pragma unroll
                    for (int g = 0; g < 4; g++) {
                        mma16816(acc[tm][2 * g],     a[tm], bf[g][0], bf[g][1]);
                        mma16816(acc[tm][2 * g + 1], a[tm], bf[g][2], bf[g][3]);
                    }
            }
        }

        __syncthreads();
        if (t == 0 && sc + 2 < 24) cv_issue(sb, mb, bi, i, oh, sc + 2);
    }

    const int r = lane >> 2, cp = (lane & 3) * 2;
    #pragma unroll
    for (int tm = 0; tm < 2; tm++) {
        #pragma unroll
        for (int tn = 0; tn < 8; tn++) {
            int oc = oh * 128 + nw * 64 + tn * 8 + cp;
            float bz0 = __ldg(bias + oc), bz1 = __ldg(bias + oc + 1);
            int j0 = mw * 32 + tm * 16 + r;
            #pragma unroll
            for (int half = 0; half < 2; half++) {
                int j = j0 + half * 8;
                float v0 = acc[tm][tn][half * 2 + 0] + bz0;
                float v1 = acc[tm][tn][half * 2 + 1] + bz1;
                size_t off = ((((size_t)b * H2 + i) * W2) + j) * C4 + oc;
                *(float2*)(g_t0 + off) = make_float2(gelu_exact(v0), gelu_exact(v1));
            }
        }
    }
}

// ---------------------------------------------------------------------------
// IDWT: t0 (fp32 NHWC) -> out (NCHW)
// ---------------------------------------------------------------------------
__global__ void idwt_kernel(float* __restrict__ out) {
    __shared__ float4 s[16][17];
    int b = blockIdx.z, h2 = blockIdx.y;
    int ctile = blockIdx.x >> 3, wtile = blockIdx.x & 7;
    int tx = threadIdx.x, ty = threadIdx.y;

    int c = ctile * 16 + tx, w2 = wtile * 16 + ty;
    s[ty][tx] = *(const float4*)(g_t0 + ((((size_t)b * H2 + w2) * W2) + h2) * C4 + 4 * c);
    __syncthreads();

    float4 v = s[tx][ty];
    int c2 = ctile * 16 + ty, w2b = wtile * 16 + tx;
    float ll = v.x, ch = v.y, cv = v.z, cd = v.w;
    float a  = (ll + ch + cv + cd) * 0.5f;
    float bq = (ll + ch - cv - cd) * 0.5f;
    float cq = (ll - ch + cv - cd) * 0.5f;
    float dq = (ll - ch - cv + cd) * 0.5f;
    float* o = out + (((size_t)(b * CC + c2) * 256) + 2 * h2) * 256 + 2 * w2b;
    *(float2*)o         = make_float2(a, bq);
    *(float2*)(o + 256) = make_float2(cq, dq);
}

// ---------------------------------------------------------------------------
extern "C" void kernel_launch(void* const* d_in, const int* in_sizes, int n_in,
                              void* d_out, int out_size) {
    const float* x    = (const float*)d_in[0];
    const float* dw_w = (const float*)d_in[1];
    const float* dw_b = (const float*)d_in[2];
    const float* pw_w = (const float*)d_in[3];
    const float* pw_b = (const float*)d_in[4];
    const float* cv_w = (const float*)d_in[5];
    const float* cv_b = (const float*)d_in[6];
    float* out = (float*)d_out;

    cudaFuncSetAttribute(pw_gemm_kernel,
                         cudaFuncAttributeMaxDynamicSharedMemorySize, SMEM_PW);
    cudaFuncSetAttribute(cv_gemm_kernel,
                         cudaFuncAttributeMaxDynamicSharedMemorySize, SMEM_CV);

    prep_kernel<<<1024, 256>>>(dw_w, pw_w, cv_w);
    dwt_kernel<<<dim3(32, 128, BB), dim3(16, 16)>>>(x);
    dw_kernel<<<dim3(32, 128, BB), dim3(64, 4)>>>(dw_b);
    pw_gemm_kernel<<<dim3(2, 1024), 256, SMEM_PW>>>(pw_b);
    cv_gemm_kernel<<<dim3(2, 1024), 256, SMEM_CV>>>(cv_b);
    idwt_kernel<<<dim3(32, 128, BB), dim3(16, 16)>>>(out);
}

// round 12
// speedup vs baseline: 6.2308x; 1.0527x over previous
#include <cuda_runtime.h>
#include <cuda_fp16.h>
#include <math.h>
#include <stdint.h>

#define BB 8
#define CC 64
#define C4 256
#define H2 128
#define W2 128

// ---------------------------------------------------------------------------
// Tile geometry: byte-exact smem images, 80B-padded rows
// ---------------------------------------------------------------------------
#define ROWP 80
#define A_T (128 * ROWP)            // 10240  A tile (128 j-rows)
#define AG_T (130 * ROWP)           // 10400  guarded A block (halo rows 0,129)
#define B_T (128 * ROWP)            // 10240  B tile (128 oc rows = one half)

// pw: 4-stage ring, single-pass chunks
#define PW_STG (A_T + B_T)          // 20480
#define PW_NST 4
#define SMEM_PW (PW_NST * PW_STG + 64)      // 81984 -> 2 CTAs/SM

// cv: 2-stage ring of super-chunks (guarded A block + 3 B tiles)
#define CV_STG (AG_T + 3 * B_T)     // 41120
#define CV_NST 2
#define SMEM_CV (CV_NST * CV_STG + 64)      // 82304 -> 2 CTAs/SM

// ---------------------------------------------------------------------------
// Global scratch
// ---------------------------------------------------------------------------
__device__ __half g_sub[(size_t)BB * H2 * W2 * C4];    // dwt out (fp16 NHWC)
__device__ __half g_cvO[(size_t)BB * H2 * W2 * C4];    // cv out, post-GELU (fp16 NHWC)
__device__ float g_dwT[9 * C4];

// packed tiles (smem images), all single fp16
__device__ __align__(128) char g_pwA[(size_t)BB * H2 * 8 * A_T];      // [b*128+i][chunk]
__device__ __align__(128) char g_pwB[8 * 2 * B_T];                    // [chunk][ochalf]
__device__ __align__(128) char g_cvA[(size_t)BB * H2 * 8 * AG_T];     // [b*128+i][kb] guarded
__device__ __align__(128) char g_cvB[72 * 2 * B_T];                   // [tap*8+kb][ochalf]
__device__ __align__(128) char g_zeroA[AG_T];                         // never written -> zeros

__device__ __forceinline__ float gelu_exact(float v) {
    return 0.5f * v * (1.0f + erff(v * 0.70710678118654752f));
}
__device__ __forceinline__ uint32_t smem_to_u32(const void* p) {
    uint32_t a;
    asm("{ .reg .u64 t; cvta.to.shared.u64 t, %1; cvt.u32.u64 %0, t; }" : "=r"(a) : "l"(p));
    return a;
}

// ---- bulk copy + mbarrier ----
__device__ __forceinline__ void bulk_g2s(uint32_t dst, const void* src,
                                         uint32_t bytes, uint32_t mbar) {
    asm volatile(
        "cp.async.bulk.shared::cluster.global.mbarrier::complete_tx::bytes "
        "[%0], [%1], %2, [%3];"
        :: "r"(dst), "l"(src), "r"(bytes), "r"(mbar) : "memory");
}
#define MBARRIER_INIT(mbar, count) \
    asm volatile("mbarrier.init.shared.b64 [%0], %1;" :: "r"((uint32_t)(mbar)), "r"((uint32_t)(count)) : "memory")
#define MBARRIER_EXPECT_TX(mbar, bytes) \
    asm volatile("mbarrier.arrive.expect_tx.shared.b64 _, [%0], %1;" :: "r"((uint32_t)(mbar)), "r"((uint32_t)(bytes)) : "memory")
#define MBARRIER_WAIT_PARITY(mbar_smem_addr, phase_parity) do { \
    uint32_t _mbar = (uint32_t)(mbar_smem_addr); \
    uint32_t _parity = (uint32_t)(phase_parity); \
    uint32_t _done; \
    asm volatile("{\n\t.reg .pred p;\n\t" \
        "mbarrier.try_wait.parity.acquire.cta.shared::cta.b64 p, [%1], %2;\n\t" \
        "selp.b32 %0, 1, 0, p;\n\t}" : "=r"(_done) : "r"(_mbar), "r"(_parity) : "memory"); \
    if (!_done) { \
        asm volatile("{\n\t.reg .pred P1;\n\t" \
            "WAIT_LOOP_%=:\n\t" \
            "mbarrier.try_wait.parity.acquire.cta.shared::cta.b64 P1, [%0], %1, 0x989680;\n\t" \
            "@P1 bra.uni WAIT_DONE_%=;\n\t" \
            "bra.uni WAIT_LOOP_%=;\n\t" \
            "WAIT_DONE_%=:\n\t}" :: "r"(_mbar), "r"(_parity) : "memory"); \
    } \
} while(0)

// ---- mma ----
__device__ __forceinline__ void ldsm4(uint32_t* r, uint32_t addr) {
    asm volatile("ldmatrix.sync.aligned.m8n8.x4.shared.b16 {%0,%1,%2,%3}, [%4];"
                 : "=r"(r[0]), "=r"(r[1]), "=r"(r[2]), "=r"(r[3]) : "r"(addr));
}
__device__ __forceinline__ void mma16816(float* c, const uint32_t* a,
                                         uint32_t b0, uint32_t b1) {
    asm volatile(
        "mma.sync.aligned.m16n8k16.row.col.f32.f16.f16.f32 "
        "{%0,%1,%2,%3}, {%4,%5,%6,%7}, {%8,%9}, {%0,%1,%2,%3};"
        : "+f"(c[0]), "+f"(c[1]), "+f"(c[2]), "+f"(c[3])
        : "r"(a[0]), "r"(a[1]), "r"(a[2]), "r"(a[3]), "r"(b0), "r"(b1));
}

// ---------------------------------------------------------------------------
// prep: dw weights, pw/cv weight tiles (single fp16 smem images)
// ---------------------------------------------------------------------------
__global__ void prep_kernel(const float* __restrict__ dw_w,
                            const float* __restrict__ pw_w,
                            const float* __restrict__ cv_w) {
    int idx0 = blockIdx.x * blockDim.x + threadIdx.x;
    int stride = gridDim.x * blockDim.x;
    for (int idx = idx0; idx < 9 * C4; idx += stride) {
        int tap = idx >> 8, c = idx & 255;
        g_dwT[idx] = dw_w[c * 9 + tap];
    }
    for (int idx = idx0; idx < C4 * C4; idx += stride) {
        int oc = idx >> 8, ic = idx & 255;
        size_t o = (size_t)((ic >> 5) * 2 + (oc >> 7)) * B_T
                 + (size_t)(oc & 127) * ROWP + (ic & 31) * 2;
        *(__half*)(g_pwB + o) = __float2half(pw_w[idx]);
    }
    for (int idx = idx0; idx < 9 * C4 * C4; idx += stride) {
        int tap = idx / (C4 * C4);
        int r = idx % (C4 * C4);
        int oc = r >> 8, ic = r & 255;
        float v = cv_w[((size_t)oc * C4 + ic) * 9 + tap];
        size_t o = (size_t)((tap * 8 + (ic >> 5)) * 2 + (oc >> 7)) * B_T
                 + (size_t)(oc & 127) * ROWP + (ic & 31) * 2;
        *(__half*)(g_cvB + o) = __float2half(v);
    }
}

// ---------------------------------------------------------------------------
// DWT + transpose:  x (NCHW fp32) -> g_sub (fp16 NHWC [b][i][j][4c+k])
// ---------------------------------------------------------------------------
__global__ void dwt_kernel(const float* __restrict__ x) {
    __shared__ float4 s[16][17];
    int b = blockIdx.z, j = blockIdx.y;
    int ctile = blockIdx.x >> 3, itile = blockIdx.x & 7;
    int tx = threadIdx.x, ty = threadIdx.y;

    int c = ctile * 16 + ty, i = itile * 16 + tx;
    const float* p = x + (((size_t)(b * CC + c) * 256) + 2 * j) * 256 + 2 * i;
    float2 top = *(const float2*)p;
    float2 bot = *(const float2*)(p + 256);
    float a = top.x, bq = top.y, cq = bot.x, d = bot.y;
    s[ty][tx] = make_float4((a + bq + cq + d) * 0.5f, (a + bq - cq - d) * 0.5f,
                            (a - bq + cq - d) * 0.5f, (a - bq - cq + d) * 0.5f);
    __syncthreads();
    float4 v = s[tx][ty];
    int c2 = ctile * 16 + tx, i2 = itile * 16 + ty;
    __half hv[4] = {__float2half(v.x), __float2half(v.y),
                    __float2half(v.z), __float2half(v.w)};
    *(uint2*)(g_sub + ((((size_t)b * H2 + i2) * W2) + j) * C4 + 4 * c2) = *(uint2*)hv;
}

// ---------------------------------------------------------------------------
// Depthwise 3x3 + bias (fp32 accum from fp16), write packed pw-A fp16 tiles
// ---------------------------------------------------------------------------
__global__ void dw_kernel(const float* __restrict__ dw_b) {
    int cq = threadIdx.x;
    int j = blockIdx.x * 4 + threadIdx.y;
    int i = blockIdx.y, b = blockIdx.z;
    int c0 = cq * 4;

    float4 acc = *(const float4*)(dw_b + c0);
    #pragma unroll
    for (int tap = 0; tap < 9; ++tap) {
        int ii = i + tap / 3 - 1, jj = j + tap % 3 - 1;
        if ((unsigned)ii < (unsigned)H2 && (unsigned)jj < (unsigned)W2) {
            uint2 hv = *(const uint2*)(g_sub + ((((size_t)b * H2 + ii) * W2) + jj) * C4 + c0);
            __half2* ph = (__half2*)&hv;
            float2 f0 = __half22float2(ph[0]);
            float2 f1 = __half22float2(ph[1]);
            float4 w = *(const float4*)(g_dwT + tap * C4 + c0);
            acc.x += f0.x * w.x; acc.y += f0.y * w.y;
            acc.z += f1.x * w.z; acc.w += f1.y * w.w;
        }
    }
    __half hb[4] = {__float2half(acc.x), __float2half(acc.y),
                    __float2half(acc.z), __float2half(acc.w)};
    size_t o = (size_t)(((b * H2 + i) * 8) + (c0 >> 5)) * A_T
             + (size_t)j * ROWP + (c0 & 31) * 2;
    *(uint2*)(g_pwA + o) = *(uint2*)hb;
}

// ---------------------------------------------------------------------------
// pw GEMM: single-pass fp16, CTA 128(j)x128(oc-half), 256 thr, 4x2 warps,
// 4-stage bulk ring (single sync/chunk), out -> packed cv-A fp16 tiles.
// ---------------------------------------------------------------------------
__device__ __forceinline__ void pw_issue(uint32_t sb, uint32_t mb,
                                         int bi, int oh, int c) {
    int s = c & 3;
    uint32_t st = sb + s * PW_STG;
    uint32_t mbar = mb + s * 8;
    MBARRIER_EXPECT_TX(mbar, PW_STG);
    bulk_g2s(st, g_pwA + (size_t)(bi * 8 + c) * A_T, A_T, mbar);
    bulk_g2s(st + A_T, g_pwB + (size_t)(c * 2 + oh) * B_T, B_T, mbar);
}

__global__ void __launch_bounds__(256, 2)
pw_gemm_kernel(const float* __restrict__ bias) {
    extern __shared__ char smem[];
    uint32_t sb = smem_to_u32(smem);
    uint32_t mb = sb + PW_NST * PW_STG;
    const int t = threadIdx.x, lane = t & 31, wid = t >> 5;
    const int mw = wid & 3, nw = wid >> 2;
    const int oh = blockIdx.x;
    const int bi = blockIdx.y;

    if (t == 0) {
        #pragma unroll
        for (int s = 0; s < PW_NST; s++) MBARRIER_INIT(mb + s * 8, 1);
    }
    __syncthreads();
    if (t == 0) {
        pw_issue(sb, mb, bi, oh, 0);
        pw_issue(sb, mb, bi, oh, 1);
        pw_issue(sb, mb, bi, oh, 2);
    }

    float acc[2][8][4];
    #pragma unroll
    for (int tm = 0; tm < 2; tm++)
        #pragma unroll
        for (int tn = 0; tn < 8; tn++)
            #pragma unroll
            for (int q = 0; q < 4; q++) acc[tm][tn][q] = 0.0f;

    uint32_t aoff[2], boff[4];
    #pragma unroll
    for (int tm = 0; tm < 2; tm++)
        aoff[tm] = (mw * 32 + tm * 16 + (lane & 15)) * ROWP + (lane >> 4) * 16;
    #pragma unroll
    for (int g = 0; g < 4; g++)
        boff[g] = (nw * 64 + g * 16 + ((lane >> 4) & 1) * 8 + (lane & 7)) * ROWP
                + ((lane >> 3) & 1) * 16;

    int parity = 0;
    for (int c = 0; c < 8; c++) {
        int s = c & 3;
        MBARRIER_WAIT_PARITY(mb + s * 8, parity);
        if (s == 3) parity ^= 1;
        __syncthreads();
        if (t == 0 && c + 3 < 8) pw_issue(sb, mb, bi, oh, c + 3);

        uint32_t st = sb + s * PW_STG;
        #pragma unroll
        for (int kh = 0; kh < 2; kh++) {
            uint32_t a[2][4], bf[4][4];
            #pragma unroll
            for (int tm = 0; tm < 2; tm++) ldsm4(a[tm], st + aoff[tm] + kh * 32);
            #pragma unroll
            for (int g = 0; g < 4; g++) ldsm4(bf[g], st + A_T + boff[g] + kh * 32);
            #pragma unroll
            for (int tm = 0; tm < 2; tm++)
                #pragma unroll
                for (int g = 0; g < 4; g++) {
                    mma16816(acc[tm][2 * g],     a[tm], bf[g][0], bf[g][1]);
                    mma16816(acc[tm][2 * g + 1], a[tm], bf[g][2], bf[g][3]);
                }
        }
    }

    const int r = lane >> 2, cp = (lane & 3) * 2;
    #pragma unroll
    for (int tm = 0; tm < 2; tm++) {
        #pragma unroll
        for (int tn = 0; tn < 8; tn++) {
            int oc = oh * 128 + nw * 64 + tn * 8 + cp;
            float bz0 = __ldg(bias + oc), bz1 = __ldg(bias + oc + 1);
            int j0 = mw * 32 + tm * 16 + r;
            #pragma unroll
            for (int half = 0; half < 2; half++) {
                int j = j0 + half * 8;
                float v0 = acc[tm][tn][half * 2 + 0] + bz0;
                float v1 = acc[tm][tn][half * 2 + 1] + bz1;
                __half hp[2] = {__float2half(v0), __float2half(v1)};
                size_t o = (size_t)((bi * 8) + (oc >> 5)) * AG_T
                         + (size_t)(j + 1) * ROWP + (oc & 31) * 2;
                *(uint32_t*)(g_cvA + o) = *(uint32_t*)hp;
            }
        }
    }
}

// ---------------------------------------------------------------------------
// cv GEMM: single-pass fp16 super-chunks. One guarded A block (130 rows)
// serves 3 taps (dj = -1,0,+1 via +80B smem base shifts). 24 super-chunks
// (di,kb), 2-stage ring, double sync. Out -> g_cvO fp16 (bias+GELU).
// ---------------------------------------------------------------------------
__device__ __forceinline__ void cv_issue(uint32_t sb, uint32_t mb,
                                         int bi, int i, int oh, int sc) {
    int s = sc & 1;
    int di = sc >> 3, kb = sc & 7;
    int ii = i + di - 1;
    uint32_t st = sb + s * CV_STG;
    uint32_t mbar = mb + s * 8;
    MBARRIER_EXPECT_TX(mbar, CV_STG);
    const char* ap = ((unsigned)ii < (unsigned)H2)
        ? g_cvA + (size_t)(((bi & ~127) + ii) * 8 + kb) * AG_T
        : g_zeroA;
    bulk_g2s(st, ap, AG_T, mbar);
    #pragma unroll
    for (int djq = 0; djq < 3; djq++) {
        int tap = di * 3 + djq;
        bulk_g2s(st + AG_T + djq * B_T,
                 g_cvB + (size_t)((tap * 8 + kb) * 2 + oh) * B_T, B_T, mbar);
    }
}

__global__ void __launch_bounds__(256, 2)
cv_gemm_kernel(const float* __restrict__ bias) {
    extern __shared__ char smem[];
    uint32_t sb = smem_to_u32(smem);
    uint32_t mb = sb + CV_NST * CV_STG;
    const int t = threadIdx.x, lane = t & 31, wid = t >> 5;
    const int mw = wid & 3, nw = wid >> 2;
    const int oh = blockIdx.x;
    const int bi = blockIdx.y;
    const int b = bi >> 7, i = bi & 127;

    if (t == 0) {
        MBARRIER_INIT(mb, 1);
        MBARRIER_INIT(mb + 8, 1);
    }
    __syncthreads();
    if (t == 0) {
        cv_issue(sb, mb, bi, i, oh, 0);
        cv_issue(sb, mb, bi, i, oh, 1);
    }

    float acc[2][8][4];
    #pragma unroll
    for (int tm = 0; tm < 2; tm++)
        #pragma unroll
        for (int tn = 0; tn < 8; tn++)
            #pragma unroll
            for (int q = 0; q < 4; q++) acc[tm][tn][q] = 0.0f;

    uint32_t aoff[2], boff[4];
    #pragma unroll
    for (int tm = 0; tm < 2; tm++)
        aoff[tm] = (mw * 32 + tm * 16 + (lane & 15)) * ROWP + (lane >> 4) * 16;
    #pragma unroll
    for (int g = 0; g < 4; g++)
        boff[g] = (nw * 64 + g * 16 + ((lane >> 4) & 1) * 8 + (lane & 7)) * ROWP
                + ((lane >> 3) & 1) * 16;

    for (int sc = 0; sc < 24; sc++) {
        int s = sc & 1;
        MBARRIER_WAIT_PARITY(mb + s * 8, (sc >> 1) & 1);
        __syncthreads();

        uint32_t st = sb + s * CV_STG;
        #pragma unroll
        for (int djq = 0; djq < 3; djq++) {
            uint32_t Ab = st + djq * ROWP;          // dj = djq-1 -> base (1+dj)*80
            uint32_t Bb = st + AG_T + djq * B_T;
            #pragma unroll
            for (int kh = 0; kh < 2; kh++) {
                uint32_t a[2][4], bf[4][4];
                #pragma unroll
                for (int tm = 0; tm < 2; tm++) ldsm4(a[tm], Ab + aoff[tm] + kh * 32);
                #pragma unroll
                for (int g = 0; g < 4; g++) ldsm4(bf[g], Bb + boff[g] + kh * 32);
                #pragma unroll
                for (int tm = 0; tm < 2; tm++)
                    #pragma unroll
                    for (int g = 0; g < 4; g++) {
                        mma16816(acc[tm][2 * g],     a[tm], bf[g][0], bf[g][1]);
                        mma16816(acc[tm][2 * g + 1], a[tm], bf[g][2], bf[g][3]);
                    }
            }
        }

        __syncthreads();
        if (t == 0 && sc + 2 < 24) cv_issue(sb, mb, bi, i, oh, sc + 2);
    }

    const int r = lane >> 2, cp = (lane & 3) * 2;
    #pragma unroll
    for (int tm = 0; tm < 2; tm++) {
        #pragma unroll
        for (int tn = 0; tn < 8; tn++) {
            int oc = oh * 128 + nw * 64 + tn * 8 + cp;
            float bz0 = __ldg(bias + oc), bz1 = __ldg(bias + oc + 1);
            int j0 = mw * 32 + tm * 16 + r;
            #pragma unroll
            for (int half = 0; half < 2; half++) {
                int j = j0 + half * 8;
                float v0 = gelu_exact(acc[tm][tn][half * 2 + 0] + bz0);
                float v1 = gelu_exact(acc[tm][tn][half * 2 + 1] + bz1);
                __half hp[2] = {__float2half(v0), __float2half(v1)};
                size_t off = ((((size_t)b * H2 + i) * W2) + j) * C4 + oc;
                *(uint32_t*)(g_cvO + off) = *(uint32_t*)hp;
            }
        }
    }
}

// ---------------------------------------------------------------------------
// IDWT: g_cvO (fp16 NHWC) -> out (fp32 NCHW)
// ---------------------------------------------------------------------------
__global__ void idwt_kernel(float* __restrict__ out) {
    __shared__ float4 s[16][17];
    int b = blockIdx.z, h2 = blockIdx.y;
    int ctile = blockIdx.x >> 3, wtile = blockIdx.x & 7;
    int tx = threadIdx.x, ty = threadIdx.y;

    int c = ctile * 16 + tx, w2 = wtile * 16 + ty;
    uint2 hv = *(const uint2*)(g_cvO + ((((size_t)b * H2 + w2) * W2) + h2) * C4 + 4 * c);
    __half2* ph = (__half2*)&hv;
    float2 f0 = __half22float2(ph[0]);
    float2 f1 = __half22float2(ph[1]);
    s[ty][tx] = make_float4(f0.x, f0.y, f1.x, f1.y);
    __syncthreads();

    float4 v = s[tx][ty];
    int c2 = ctile * 16 + ty, w2b = wtile * 16 + tx;
    float ll = v.x, ch = v.y, cv = v.z, cd = v.w;
    float a  = (ll + ch + cv + cd) * 0.5f;
    float bq = (ll + ch - cv - cd) * 0.5f;
    float cq = (ll - ch + cv - cd) * 0.5f;
    float dq = (ll - ch - cv + cd) * 0.5f;
    float* o = out + (((size_t)(b * CC + c2) * 256) + 2 * h2) * 256 + 2 * w2b;
    *(float2*)o         = make_float2(a, bq);
    *(float2*)(o + 256) = make_float2(cq, dq);
}

// ---------------------------------------------------------------------------
extern "C" void kernel_launch(void* const* d_in, const int* in_sizes, int n_in,
                              void* d_out, int out_size) {
    const float* x    = (const float*)d_in[0];
    const float* dw_w = (const float*)d_in[1];
    const float* dw_b = (const float*)d_in[2];
    const float* pw_w = (const float*)d_in[3];
    const float* pw_b = (const float*)d_in[4];
    const float* cv_w = (const float*)d_in[5];
    const float* cv_b = (const float*)d_in[6];
    float* out = (float*)d_out;

    cudaFuncSetAttribute(pw_gemm_kernel,
                         cudaFuncAttributeMaxDynamicSharedMemorySize, SMEM_PW);
    cudaFuncSetAttribute(cv_gemm_kernel,
                         cudaFuncAttributeMaxDynamicSharedMemorySize, SMEM_CV);

    prep_kernel<<<1024, 256>>>(dw_w, pw_w, cv_w);
    dwt_kernel<<<dim3(32, 128, BB), dim3(16, 16)>>>(x);
    dw_kernel<<<dim3(32, 128, BB), dim3(64, 4)>>>(dw_b);
    pw_gemm_kernel<<<dim3(2, 1024), 256, SMEM_PW>>>(pw_b);
    cv_gemm_kernel<<<dim3(2, 1024), 256, SMEM_CV>>>(cv_b);
    idwt_kernel<<<dim3(32, 128, BB), dim3(16, 16)>>>(out);
}